// round 10
// baseline (speedup 1.0000x reference)
#include <cuda_runtime.h>
#include <cuda_fp16.h>
#include <math.h>
#include <stdint.h>

// ---------------- packed fp16 weights ----------------
// g_w2: fragment-ordered: [m4][nq4][kt32][nw4][grp2][lane32][4 halves]
//       lane block (16B) = {b0,b1 of nt_even, b0,b1 of nt_odd}
// g_w1: [m4][n512][k16]  (k10 = b1) = 32,768 halves
// g_hd: [m4][n32][k512]  (n: 0-2 pos, 3-11 coef, 12-20 cov, 21 attn, 22-31 zero)
__device__ __align__(16) __half g_w2[1048576];
__device__ __align__(16) __half g_w1[32768];
__device__ __align__(16) __half g_hd[65536];
// head partials: [g*4+nq (36)][sample (32768)][22] f32
__device__ float g_part[36 * 32768 * 22];

struct PM {
  const float *tokens;
  const float *ent_b2, *pad_b2;
};
struct PE {
  const float *tokens;
  const float *ent_bpos, *ent_bc, *ent_bv;
  const float *b_bpos, *b_bc, *b_bv;
  const float *gs_W, *gs_b;
  float *out;
};

__global__ void pack_kernel(const float* eW2, const float* pW2,
                            const float* eW1, const float* eb1,
                            const float* pW1, const float* pb1,
                            const float* eWpos, const float* eWc, const float* eWv,
                            const float* bWpos, const float* bWc, const float* bWv,
                            const float* attnW) {
  int tid = blockIdx.x * blockDim.x + threadIdx.x;
  int NT = gridDim.x * blockDim.x;
  for (int idx = tid; idx < 4 * 512 * 512; idx += NT) {
    int m = idx >> 18, r = idx & 262143, k = r >> 9, n = r & 511;
    float v = (m < 3) ? eW2[m * 262144 + k * 512 + n] : pW2[k * 512 + n];
    int nq = n >> 7, nl = n & 127;
    int nw = nl >> 5, nt = (nl >> 3) & 3;
    int grp = nt >> 1, odd = nt & 1;
    int kt = k >> 4, kk = k & 15;
    int lane = (nl & 7) * 4 + ((kk & 7) >> 1);
    int dst = ((((m * 4 + nq) * 32 + kt) * 4 + nw) * 2 + grp) * 256 +
              lane * 8 + odd * 4 + ((kk >> 3) & 1) * 2 + (kk & 1);
    g_w2[dst] = __float2half(v);
  }
  for (int idx = tid; idx < 4 * 512 * 16; idx += NT) {
    int m = idx >> 13, r = idx & 8191, n = r >> 4, k = r & 15;
    float v = 0.f;
    if (k < 10)       v = (m < 3) ? eW1[m * 5120 + k * 512 + n] : pW1[k * 512 + n];
    else if (k == 10) v = (m < 3) ? eb1[m * 512 + n] : pb1[n];
    g_w1[(m * 512 + n) * 16 + k] = __float2half(v);
  }
  for (int idx = tid; idx < 4 * 32 * 512; idx += NT) {
    int m = idx >> 14, r = idx & 16383, n = r >> 9, k = r & 511;
    float v = 0.f;
    if (m < 3) {
      if (n < 3)       v = eWpos[m * 1536 + k * 3 + n];
      else if (n < 12) v = eWc[m * 4608 + k * 9 + (n - 3)];
      else if (n < 21) v = eWv[m * 4608 + k * 9 + (n - 12)];
    } else {
      if (n < 3)       v = bWpos[k * 3 + n];
      else if (n < 12) v = bWc[k * 9 + (n - 3)];
      else if (n < 21) v = bWv[k * 9 + (n - 12)];
      else if (n == 21) v = attnW[k];
    }
    g_hd[(m * 32 + n) * 512 + k] = __float2half(v);
  }
}

// ---------------- mma helpers ----------------
__device__ __forceinline__ void ldsm4(uint32_t a, uint32_t& r0, uint32_t& r1,
                                      uint32_t& r2, uint32_t& r3) {
  asm volatile("ldmatrix.sync.aligned.m8n8.x4.shared.b16 {%0,%1,%2,%3}, [%4];"
               : "=r"(r0), "=r"(r1), "=r"(r2), "=r"(r3) : "r"(a));
}
__device__ __forceinline__ void mma16816(float* c, uint32_t a0, uint32_t a1,
                                         uint32_t a2, uint32_t a3,
                                         uint32_t b0, uint32_t b1) {
  asm volatile(
      "mma.sync.aligned.m16n8k16.row.col.f32.f16.f16.f32 "
      "{%0,%1,%2,%3},{%4,%5,%6,%7},{%8,%9},{%0,%1,%2,%3};"
      : "+f"(c[0]), "+f"(c[1]), "+f"(c[2]), "+f"(c[3])
      : "r"(a0), "r"(a1), "r"(a2), "r"(a3), "r"(b0), "r"(b1));
}

// ---------------- swizzled A-tile addressing ----------------
__device__ __forceinline__ int swA(int row, int kbyte) {
  return (row * 1024 + kbyte) ^ ((row & 7) << 4);
}

// ---------------- smem layout (bytes) ----------------
#define NTH 256
static constexpr int OF_A  = 0;        // A/h1/h2 tile: 64 rows x 1024B, swizzled = 65,536
static constexpr int OF_R  = 65536;    // overlay: W1T (512x48B=24,576)+x-tile [prologue]
                                       //          heads B (32x272B=8,704)+s_part [tail]
static constexpr int OF_XT = OF_R + 24576;  // 2048
static constexpr int OF_HB = OF_R;
static constexpr int OF_P  = OF_R + 17408;  // 6,144
static constexpr int SMEM_SZ = 92160;  // 90 KB -> 2 CTAs/SM

__device__ __forceinline__ float softplusf(float x) { return (x > 20.f) ? x : log1pf(expf(x)); }

__global__ void __launch_bounds__(NTH, 2) spectral_mma_kernel(PM p) {
  extern __shared__ __align__(128) unsigned char sm[];
  const uint32_t smb = (uint32_t)__cvta_generic_to_shared(sm);
  const int t = threadIdx.x, wid = t >> 5, lane = t & 31;
  const int g = blockIdx.y, nq = blockIdx.z;
  const int m = (g < 3) ? g : 3;
  const int s0 = blockIdx.x * 64;
  const int mw = wid & 1, nw = wid >> 1;                // 2 M-warps x 4 N-warps (64 x 128)
  const int ag_r = ((lane >> 3) & 1) * 8 + (lane & 7);  // A ldsm: row offset
  const int ag_k = ((lane >> 4) & 1) * 8;               // A ldsm: k offset
  const int bg_n = ((lane >> 4) & 1) * 8 + (lane & 7);  // B ldsm: n offset (heads only)
  const int bg_k = ((lane >> 3) & 1) * 8;               // B ldsm: k offset (heads only)
  const int lr = lane >> 2, lc2 = (lane & 3) * 2;       // C frag mapping

  // ---- prologue: build x-tile + park W1T in overlay ----
  for (int i = t; i < 64 * 16; i += NTH) {
    int s = i >> 4, k = i & 15;
    float v = (k < 10) ? p.tokens[(size_t)(s0 + s) * 100 + g * 10 + k] : (k == 10 ? 1.f : 0.f);
    *(__half*)(sm + OF_XT + s * 32 + k * 2) = __float2half(v);
  }
  for (int u = t; u < 1024; u += NTH)    // W1T: 512 rows x 32B data, 48B stride
    *(uint4*)(sm + OF_R + (u >> 1) * 48 + (u & 1) * 16) =
        *(const uint4*)((const char*)g_w1 + m * 16384 + u * 16);
  __syncthreads();

  // ---- phase A: h1 = relu(x @ W1T) -> swizzled A-tile (full 512 cols) ----
  {
    uint32_t xa[2][4];
    ldsm4(smb + OF_XT + (mw * 32 + ag_r) * 32 + ag_k * 2, xa[0][0], xa[0][1], xa[0][2], xa[0][3]);
    ldsm4(smb + OF_XT + (mw * 32 + 16 + ag_r) * 32 + ag_k * 2, xa[1][0], xa[1][1], xa[1][2], xa[1][3]);
#pragma unroll
    for (int pss = 0; pss < 2; ++pss) {
#pragma unroll
      for (int pq = 0; pq < 4; ++pq) {
        uint32_t b[4];
        int nr = pss * 256 + nw * 64 + pq * 16 + bg_n;
        ldsm4(smb + OF_R + nr * 48 + bg_k * 2, b[0], b[1], b[2], b[3]);
        float pa[2][2][4];
#pragma unroll
        for (int mt = 0; mt < 2; ++mt)
#pragma unroll
          for (int tn = 0; tn < 2; ++tn) {
#pragma unroll
            for (int i = 0; i < 4; ++i) pa[mt][tn][i] = 0.f;
            mma16816(pa[mt][tn], xa[mt][0], xa[mt][1], xa[mt][2], xa[mt][3],
                     b[tn * 2], b[tn * 2 + 1]);
          }
#pragma unroll
        for (int mt = 0; mt < 2; ++mt)
#pragma unroll
          for (int tn = 0; tn < 2; ++tn) {
            int col = pss * 256 + nw * 64 + pq * 16 + tn * 8 + lc2;
            int row0 = mw * 32 + mt * 16 + lr;
            *(__half2*)(sm + OF_A + swA(row0, col * 2)) =
                __floats2half2_rn(fmaxf(pa[mt][tn][0], 0.f), fmaxf(pa[mt][tn][1], 0.f));
            *(__half2*)(sm + OF_A + swA(row0 + 8, col * 2)) =
                __floats2half2_rn(fmaxf(pa[mt][tn][2], 0.f), fmaxf(pa[mt][tn][3], 0.f));
          }
      }
    }
  }
  __syncthreads();   // h1 complete; A-tile read-only from here -> NO MORE SYNCS in mainloop

  // ---- GEMM1 mainloop: 32 k16 steps, B fragments via LDG.128, barrier-free ----
  float acc[2][4][4];
#pragma unroll
  for (int mt = 0; mt < 2; ++mt)
#pragma unroll
    for (int nt = 0; nt < 4; ++nt)
#pragma unroll
      for (int i = 0; i < 4; ++i) acc[mt][nt][i] = 0.f;

  const char* wbase = (const char*)g_w2 +
      (size_t)(m * 4 + nq) * 131072 +      // per (m,nq): 32 kt x 4096 B
      nw * 1024 + lane * 16;               // per nw: 2 grp x 512 B
  uint4 bc0 = *(const uint4*)(wbase);
  uint4 bc1 = *(const uint4*)(wbase + 512);
#pragma unroll 4
  for (int kt = 0; kt < 32; ++kt) {
    uint4 bn0, bn1;
    if (kt < 31) {
      bn0 = *(const uint4*)(wbase + (kt + 1) * 4096);
      bn1 = *(const uint4*)(wbase + (kt + 1) * 4096 + 512);
    }
    uint32_t A0[4], A1[4];
    ldsm4(smb + OF_A + swA(mw * 32 + ag_r, (kt * 16 + ag_k) * 2), A0[0], A0[1], A0[2], A0[3]);
    ldsm4(smb + OF_A + swA(mw * 32 + 16 + ag_r, (kt * 16 + ag_k) * 2), A1[0], A1[1], A1[2], A1[3]);
    // grp 0: n-tiles 0,1 ; grp 1: n-tiles 2,3
    mma16816(acc[0][0], A0[0], A0[1], A0[2], A0[3], bc0.x, bc0.y);
    mma16816(acc[1][0], A1[0], A1[1], A1[2], A1[3], bc0.x, bc0.y);
    mma16816(acc[0][1], A0[0], A0[1], A0[2], A0[3], bc0.z, bc0.w);
    mma16816(acc[1][1], A1[0], A1[1], A1[2], A1[3], bc0.z, bc0.w);
    mma16816(acc[0][2], A0[0], A0[1], A0[2], A0[3], bc1.x, bc1.y);
    mma16816(acc[1][2], A1[0], A1[1], A1[2], A1[3], bc1.x, bc1.y);
    mma16816(acc[0][3], A0[0], A0[1], A0[2], A0[3], bc1.z, bc1.w);
    mma16816(acc[1][3], A1[0], A1[1], A1[2], A1[3], bc1.z, bc1.w);
    bc0 = bn0; bc1 = bn1;
  }
  __syncthreads();   // all A-tile reads done; safe to overwrite with h2

  // ---- h2 (bias+relu) -> A-tile cols 0..127 (local), heads B copy, zero s_part ----
  {
    const float* b2 = (g < 3) ? (p.ent_b2 + m * 512) : p.pad_b2;
#pragma unroll
    for (int mt = 0; mt < 2; ++mt)
#pragma unroll
      for (int nt = 0; nt < 4; ++nt) {
        int lcol = nw * 32 + nt * 8 + lc2;
        float bb0 = __ldg(b2 + nq * 128 + lcol), bb1 = __ldg(b2 + nq * 128 + lcol + 1);
        int row0 = mw * 32 + mt * 16 + lr;
        *(__half2*)(sm + OF_A + swA(row0, lcol * 2)) =
            __floats2half2_rn(fmaxf(acc[mt][nt][0] + bb0, 0.f), fmaxf(acc[mt][nt][1] + bb1, 0.f));
        *(__half2*)(sm + OF_A + swA(row0 + 8, lcol * 2)) =
            __floats2half2_rn(fmaxf(acc[mt][nt][2] + bb0, 0.f), fmaxf(acc[mt][nt][3] + bb1, 0.f));
      }
  }
  for (int u = t; u < 512; u += NTH) {   // heads B: 32 n x 128 k halves, stride 272B
    int n = u >> 4, kq = u & 15;
    *(uint4*)(sm + OF_HB + n * 272 + kq * 16) =
        *(const uint4*)(g_hd + (size_t)(m * 32 + n) * 512 + nq * 128 + kq * 8);
  }
  for (int i = t; i < 64 * 24; i += NTH) ((float*)(sm + OF_P))[i] = 0.f;
  __syncthreads();

  // ---- heads GEMM: warp = (mw strip) x (k-slice nw of 32), n=24 ----
  {
    float hacc[2][3][4];
#pragma unroll
    for (int mt = 0; mt < 2; ++mt)
#pragma unroll
      for (int nt = 0; nt < 3; ++nt)
#pragma unroll
        for (int i = 0; i < 4; ++i) hacc[mt][nt][i] = 0.f;
#pragma unroll
    for (int q = 0; q < 2; ++q) {
      int koff = nw * 32 + q * 16;
      uint32_t A0[4], A1[4], b0[4], b1[4];
      ldsm4(smb + OF_A + swA(mw * 32 + ag_r, (koff + ag_k) * 2), A0[0], A0[1], A0[2], A0[3]);
      ldsm4(smb + OF_A + swA(mw * 32 + 16 + ag_r, (koff + ag_k) * 2), A1[0], A1[1], A1[2], A1[3]);
      ldsm4(smb + OF_HB + bg_n * 272 + (koff + bg_k) * 2, b0[0], b0[1], b0[2], b0[3]);
      ldsm4(smb + OF_HB + (16 + bg_n) * 272 + (koff + bg_k) * 2, b1[0], b1[1], b1[2], b1[3]);
      mma16816(hacc[0][0], A0[0], A0[1], A0[2], A0[3], b0[0], b0[1]);
      mma16816(hacc[0][1], A0[0], A0[1], A0[2], A0[3], b0[2], b0[3]);
      mma16816(hacc[0][2], A0[0], A0[1], A0[2], A0[3], b1[0], b1[1]);
      mma16816(hacc[1][0], A1[0], A1[1], A1[2], A1[3], b0[0], b0[1]);
      mma16816(hacc[1][1], A1[0], A1[1], A1[2], A1[3], b0[2], b0[3]);
      mma16816(hacc[1][2], A1[0], A1[1], A1[2], A1[3], b1[0], b1[1]);
    }
    float* sp = (float*)(sm + OF_P);
#pragma unroll
    for (int mt = 0; mt < 2; ++mt)
#pragma unroll
      for (int nt = 0; nt < 3; ++nt) {
        int row0 = mw * 32 + mt * 16 + lr, col = nt * 8 + lc2;
        atomicAdd(sp + row0 * 24 + col,           hacc[mt][nt][0]);
        atomicAdd(sp + row0 * 24 + col + 1,       hacc[mt][nt][1]);
        atomicAdd(sp + (row0 + 8) * 24 + col,     hacc[mt][nt][2]);
        atomicAdd(sp + (row0 + 8) * 24 + col + 1, hacc[mt][nt][3]);
      }
  }
  __syncthreads();

  for (int i = t; i < 64 * 22; i += NTH) {
    int s = i / 22, c = i - s * 22;
    g_part[((size_t)(g * 4 + nq) * 32768 + s0 + s) * 22 + c] = ((float*)(sm + OF_P))[s * 24 + c];
  }
}

__global__ void epilogue_kernel(PE p, int B) {
  int s = blockIdx.x * blockDim.x + threadIdx.x;
  if (s >= B) return;
  float hd[9][22];
#pragma unroll
  for (int q = 0; q < 9; ++q) {
#pragma unroll
    for (int c = 0; c < 22; ++c) hd[q][c] = 0.f;
#pragma unroll
    for (int nq = 0; nq < 4; ++nq) {
      const float* pp = g_part + ((size_t)(q * 4 + nq) * 32768 + s) * 22;
#pragma unroll
      for (int c = 0; c < 22; ++c) hd[q][c] += pp[c];
    }
  }
  float mx = -1e30f;
#pragma unroll
  for (int q = 3; q < 9; ++q) mx = fmaxf(mx, hd[q][21]);
  float den = 0.f, agg[21];
#pragma unroll
  for (int c = 0; c < 21; ++c) agg[c] = 0.f;
#pragma unroll
  for (int q = 3; q < 9; ++q) {
    float w = expf(hd[q][21] - mx);
    den += w;
#pragma unroll
    for (int c = 0; c < 21; ++c) agg[c] = fmaf(w, hd[q][c], agg[c]);
  }
  float inv = 1.f / den;

  float* o = p.out + (size_t)s * 105;
  float pos[4][3], coef[4][9], cov[4][9];
  for (int e = 0; e < 3; ++e) {
    for (int d = 0; d < 3; ++d) pos[e][d]  = hd[e][d] + p.ent_bpos[e * 3 + d];
    for (int c = 0; c < 9; ++c) coef[e][c] = hd[e][3 + c] + p.ent_bc[e * 9 + c];
    for (int c = 0; c < 9; ++c) cov[e][c]  = softplusf(hd[e][12 + c] + p.ent_bv[e * 9 + c]);
  }
  for (int d = 0; d < 3; ++d) pos[3][d]  = agg[d] * inv + p.b_bpos[d];
  for (int c = 0; c < 9; ++c) coef[3][c] = agg[3 + c] * inv + p.b_bc[c];
  for (int c = 0; c < 9; ++c) cov[3][c]  = softplusf(agg[12 + c] * inv + p.b_bv[c]);
  for (int i = 0; i < 4; ++i) {
    float x = pos[i][0], y = pos[i][1], z = pos[i][2];
    for (int c = 0; c < 9; ++c) o[i * 24 + c]     = coef[i][c];
    for (int c = 0; c < 9; ++c) o[i * 24 + 9 + c] = cov[i][c];
    o[i * 24 + 18] = (4096.f - x) * 1e-3f;
    o[i * 24 + 19] = (4096.f + x) * 1e-3f;
    o[i * 24 + 20] = (5120.f - y) * 1e-3f;
    o[i * 24 + 21] = (5120.f + y) * 1e-3f;
    o[i * 24 + 22] = z * 1e-3f;
    o[i * 24 + 23] = (2044.f - z) * 1e-3f;
  }
  const int iu[6] = {0, 0, 0, 1, 1, 2}, ju[6] = {1, 2, 3, 2, 3, 3};
  for (int q = 0; q < 6; ++q) {
    int i = iu[q], j = ju[q];
    float d2 = 0.f, cd = 0.f;
    for (int d = 0; d < 3; ++d) { float df = pos[i][d] - pos[j][d]; d2 = fmaf(df, df, d2); }
    for (int c = 0; c < 9; ++c) cd = fmaf(coef[i][c], coef[j][c], cd);
    o[96 + q] = expf(-2.f * d2) * cd;
  }
  for (int d = 0; d < 3; ++d) {
    float ga = p.gs_b[d];
    for (int k = 0; k < 10; ++k)
      ga = fmaf(p.tokens[(size_t)s * 100 + 90 + k], p.gs_W[k * 3 + d], ga);
    o[102 + d] = ga;
  }
}

extern "C" void kernel_launch(void* const* d_in, const int* in_sizes, int n_in,
                              void* d_out, int out_size) {
  pack_kernel<<<512, 256>>>(
      (const float*)d_in[3],  (const float*)d_in[13],
      (const float*)d_in[1],  (const float*)d_in[2],
      (const float*)d_in[11], (const float*)d_in[12],
      (const float*)d_in[5],  (const float*)d_in[7],  (const float*)d_in[9],
      (const float*)d_in[17], (const float*)d_in[19], (const float*)d_in[21],
      (const float*)d_in[15]);

  int B = in_sizes[0] / 100;

  PM pm;
  pm.tokens = (const float*)d_in[0];
  pm.ent_b2 = (const float*)d_in[4];
  pm.pad_b2 = (const float*)d_in[14];
  cudaFuncSetAttribute(spectral_mma_kernel, cudaFuncAttributeMaxDynamicSharedMemorySize, SMEM_SZ);
  dim3 grid(B / 64, 9, 4);
  spectral_mma_kernel<<<grid, NTH, SMEM_SZ>>>(pm);

  PE pe;
  pe.tokens = (const float*)d_in[0];
  pe.ent_bpos = (const float*)d_in[6];
  pe.ent_bc = (const float*)d_in[8];
  pe.ent_bv = (const float*)d_in[10];
  pe.b_bpos = (const float*)d_in[18];
  pe.b_bc = (const float*)d_in[20];
  pe.b_bv = (const float*)d_in[22];
  pe.gs_W = (const float*)d_in[23];
  pe.gs_b = (const float*)d_in[24];
  pe.out = (float*)d_out;
  epilogue_kernel<<<(B + 127) / 128, 128>>>(pe, B);
}

// round 11
// speedup vs baseline: 1.2099x; 1.2099x over previous
#include <cuda_runtime.h>
#include <cuda_fp16.h>
#include <math.h>
#include <stdint.h>

// ---------------- packed fp16 weights (all fragment-ordered for direct LDG) ----
// g_w2: [m4][nq4][kt32][nw4][grp2][lane32][4 halves]
// g_w1: [m4][w8][pq4][lane32][8 halves]   (k10 = b1 folded; phase-A B frags)
// g_hd: [m4][nq4][nw4][q2][tp2][lane32][4 halves] (heads B frags)
__device__ __align__(16) __half g_w2[1048576];
__device__ __align__(16) __half g_w1[32768];
__device__ __align__(16) __half g_hd[65536];
// head partials: [g*4+nq (36)][sample (32768)][22] f32
__device__ float g_part[36 * 32768 * 22];

struct PM {
  const float *tokens;
  const float *ent_b2, *pad_b2;
};
struct PE {
  const float *tokens;
  const float *ent_bpos, *ent_bc, *ent_bv;
  const float *b_bpos, *b_bc, *b_bv;
  const float *gs_W, *gs_b;
  float *out;
};

__global__ void pack_kernel(const float* eW2, const float* pW2,
                            const float* eW1, const float* eb1,
                            const float* pW1, const float* pb1,
                            const float* eWpos, const float* eWc, const float* eWv,
                            const float* bWpos, const float* bWc, const float* bWv,
                            const float* attnW) {
  int tid = blockIdx.x * blockDim.x + threadIdx.x;
  int NT = gridDim.x * blockDim.x;
  for (int idx = tid; idx < 4 * 512 * 512; idx += NT) {
    int m = idx >> 18, r = idx & 262143, k = r >> 9, n = r & 511;
    float v = (m < 3) ? eW2[m * 262144 + k * 512 + n] : pW2[k * 512 + n];
    int nq = n >> 7, nl = n & 127;
    int nw = nl >> 5, nt = (nl >> 3) & 3;
    int grp = nt >> 1, odd = nt & 1;
    int kt = k >> 4, kk = k & 15;
    int lane = (nl & 7) * 4 + ((kk & 7) >> 1);
    int dst = ((((m * 4 + nq) * 32 + kt) * 4 + nw) * 2 + grp) * 256 +
              lane * 8 + odd * 4 + ((kk >> 3) & 1) * 2 + (kk & 1);
    g_w2[dst] = __float2half(v);
  }
  for (int idx = tid; idx < 4 * 512 * 16; idx += NT) {
    int m = idx >> 13, r = idx & 8191, n = r >> 4, k = r & 15;
    float v = 0.f;
    if (k < 10)       v = (m < 3) ? eW1[m * 5120 + k * 512 + n] : pW1[k * 512 + n];
    else if (k == 10) v = (m < 3) ? eb1[m * 512 + n] : pb1[n];
    int w = n >> 6, pq = (n >> 4) & 3, odd = (n >> 3) & 1;
    int lane = (n & 7) * 4 + ((k & 7) >> 1);
    int dst = ((m * 8 + w) * 4 + pq) * 256 + lane * 8 + odd * 4 + ((k >> 3) & 1) * 2 + (k & 1);
    g_w1[dst] = __float2half(v);
  }
  for (int idx = tid; idx < 4 * 32 * 512; idx += NT) {
    int m = idx >> 14, r = idx & 16383, n = r >> 9, k = r & 511;
    float v = 0.f;
    if (m < 3) {
      if (n < 3)       v = eWpos[m * 1536 + k * 3 + n];
      else if (n < 12) v = eWc[m * 4608 + k * 9 + (n - 3)];
      else if (n < 21) v = eWv[m * 4608 + k * 9 + (n - 12)];
    } else {
      if (n < 3)       v = bWpos[k * 3 + n];
      else if (n < 12) v = bWc[k * 9 + (n - 3)];
      else if (n < 21) v = bWv[k * 9 + (n - 12)];
      else if (n == 21) v = attnW[k];
    }
    int nq = k >> 7, kl = k & 127;
    int nw = kl >> 5, q = (kl >> 4) & 1, kk = kl & 15;
    int tp = n >> 4, odd = (n >> 3) & 1;
    int lane = (n & 7) * 4 + ((kk & 7) >> 1);
    int dst = ((((m * 4 + nq) * 4 + nw) * 2 + q) * 2 + tp) * 256 +
              lane * 8 + odd * 4 + ((kk >> 3) & 1) * 2 + (kk & 1);
    g_hd[dst] = __float2half(v);
  }
}

// ---------------- mma helpers ----------------
__device__ __forceinline__ void ldsm4(uint32_t a, uint32_t& r0, uint32_t& r1,
                                      uint32_t& r2, uint32_t& r3) {
  asm volatile("ldmatrix.sync.aligned.m8n8.x4.shared.b16 {%0,%1,%2,%3}, [%4];"
               : "=r"(r0), "=r"(r1), "=r"(r2), "=r"(r3) : "r"(a));
}
__device__ __forceinline__ void mma16816(float* c, uint32_t a0, uint32_t a1,
                                         uint32_t a2, uint32_t a3,
                                         uint32_t b0, uint32_t b1) {
  asm volatile(
      "mma.sync.aligned.m16n8k16.row.col.f32.f16.f16.f32 "
      "{%0,%1,%2,%3},{%4,%5,%6,%7},{%8,%9},{%0,%1,%2,%3};"
      : "+f"(c[0]), "+f"(c[1]), "+f"(c[2]), "+f"(c[3])
      : "r"(a0), "r"(a1), "r"(a2), "r"(a3), "r"(b0), "r"(b1));
}

__device__ __forceinline__ int swA(int row, int kbyte) {
  return (row * 1024 + kbyte) ^ ((row & 7) << 4);
}

// ---------------- smem layout ----------------
#define NTH 256
static constexpr int OF_A  = 0;        // A/h1/h2 tile: 64 rows x 1024B swizzled = 65,536
static constexpr int OF_SC = 65536;    // scratch 6,144: x-tile (2KB, phase A) / s_part (6KB, tail)
static constexpr int SMEM_SZ = 71680;  // 70 KB -> 3 CTAs/SM

__device__ __forceinline__ float softplusf(float x) { return (x > 20.f) ? x : log1pf(expf(x)); }

__global__ void __launch_bounds__(NTH, 3) spectral_mma_kernel(PM p) {
  extern __shared__ __align__(128) unsigned char sm[];
  const uint32_t smb = (uint32_t)__cvta_generic_to_shared(sm);
  const int t = threadIdx.x, wid = t >> 5, lane = t & 31;
  const int g = blockIdx.y, nq = blockIdx.z;
  const int m = (g < 3) ? g : 3;
  const int s0 = blockIdx.x * 64;
  const int mw = wid & 1, nw = wid >> 1;                // mainloop: 2 M-warps x 4 N-warps (64x128)
  const int ag_r = ((lane >> 3) & 1) * 8 + (lane & 7);  // A ldsm: row offset
  const int ag_k = ((lane >> 4) & 1) * 8;               // A ldsm: k offset
  const int lr = lane >> 2, lc2 = (lane & 3) * 2;       // C frag mapping

  // ---- prologue: build x-tile (64x16, ones at k=10) ----
  for (int i = t; i < 64 * 16; i += NTH) {
    int s = i >> 4, k = i & 15;
    float v = (k < 10) ? p.tokens[(size_t)(s0 + s) * 100 + g * 10 + k] : (k == 10 ? 1.f : 0.f);
    *(__half*)(sm + OF_SC + s * 32 + k * 2) = __float2half(v);
  }
  __syncthreads();

  // ---- phase A: h1 = relu(x @ W1T) -> swizzled A-tile; warp wid covers cols wid*64.. ----
  {
    uint32_t xa[4][4];
#pragma unroll
    for (int mt = 0; mt < 4; ++mt)
      ldsm4(smb + OF_SC + (mt * 16 + ag_r) * 32 + ag_k * 2,
            xa[mt][0], xa[mt][1], xa[mt][2], xa[mt][3]);
    const uint4* w1f = (const uint4*)((const char*)g_w1 + (size_t)(m * 8 + wid) * 2048) + lane;
#pragma unroll
    for (int pq = 0; pq < 4; ++pq) {
      uint4 bf = w1f[pq * 32];
      float pa[4][2][4];
#pragma unroll
      for (int mt = 0; mt < 4; ++mt) {
#pragma unroll
        for (int tn = 0; tn < 2; ++tn)
#pragma unroll
          for (int i = 0; i < 4; ++i) pa[mt][tn][i] = 0.f;
        mma16816(pa[mt][0], xa[mt][0], xa[mt][1], xa[mt][2], xa[mt][3], bf.x, bf.y);
        mma16816(pa[mt][1], xa[mt][0], xa[mt][1], xa[mt][2], xa[mt][3], bf.z, bf.w);
      }
#pragma unroll
      for (int mt = 0; mt < 4; ++mt)
#pragma unroll
        for (int tn = 0; tn < 2; ++tn) {
          int col = wid * 64 + pq * 16 + tn * 8 + lc2;
          int row0 = mt * 16 + lr;
          *(__half2*)(sm + OF_A + swA(row0, col * 2)) =
              __floats2half2_rn(fmaxf(pa[mt][tn][0], 0.f), fmaxf(pa[mt][tn][1], 0.f));
          *(__half2*)(sm + OF_A + swA(row0 + 8, col * 2)) =
              __floats2half2_rn(fmaxf(pa[mt][tn][2], 0.f), fmaxf(pa[mt][tn][3], 0.f));
        }
    }
  }
  __syncthreads();   // h1 complete; A-tile read-only -> barrier-free mainloop

  // ---- GEMM1 mainloop: 32 k16 steps, B frags via LDG.128 ----
  float acc[2][4][4];
#pragma unroll
  for (int mt = 0; mt < 2; ++mt)
#pragma unroll
    for (int nt = 0; nt < 4; ++nt)
#pragma unroll
      for (int i = 0; i < 4; ++i) acc[mt][nt][i] = 0.f;

  const char* wbase = (const char*)g_w2 +
      (size_t)(m * 4 + nq) * 131072 + nw * 1024 + lane * 16;
  uint4 bc0 = *(const uint4*)(wbase);
  uint4 bc1 = *(const uint4*)(wbase + 512);
#pragma unroll 4
  for (int kt = 0; kt < 32; ++kt) {
    uint4 bn0, bn1;
    if (kt < 31) {
      bn0 = *(const uint4*)(wbase + (kt + 1) * 4096);
      bn1 = *(const uint4*)(wbase + (kt + 1) * 4096 + 512);
    }
    uint32_t A0[4], A1[4];
    ldsm4(smb + OF_A + swA(mw * 32 + ag_r, (kt * 16 + ag_k) * 2), A0[0], A0[1], A0[2], A0[3]);
    ldsm4(smb + OF_A + swA(mw * 32 + 16 + ag_r, (kt * 16 + ag_k) * 2), A1[0], A1[1], A1[2], A1[3]);
    mma16816(acc[0][0], A0[0], A0[1], A0[2], A0[3], bc0.x, bc0.y);
    mma16816(acc[1][0], A1[0], A1[1], A1[2], A1[3], bc0.x, bc0.y);
    mma16816(acc[0][1], A0[0], A0[1], A0[2], A0[3], bc0.z, bc0.w);
    mma16816(acc[1][1], A1[0], A1[1], A1[2], A1[3], bc0.z, bc0.w);
    mma16816(acc[0][2], A0[0], A0[1], A0[2], A0[3], bc1.x, bc1.y);
    mma16816(acc[1][2], A1[0], A1[1], A1[2], A1[3], bc1.x, bc1.y);
    mma16816(acc[0][3], A0[0], A0[1], A0[2], A0[3], bc1.z, bc1.w);
    mma16816(acc[1][3], A1[0], A1[1], A1[2], A1[3], bc1.z, bc1.w);
    bc0 = bn0; bc1 = bn1;
  }
  __syncthreads();   // all A reads done; safe to overwrite with h2

  // ---- h2 (bias+relu) -> A-tile cols 0..127; zero s_part ----
  {
    const float* b2 = (g < 3) ? (p.ent_b2 + m * 512) : p.pad_b2;
#pragma unroll
    for (int mt = 0; mt < 2; ++mt)
#pragma unroll
      for (int nt = 0; nt < 4; ++nt) {
        int lcol = nw * 32 + nt * 8 + lc2;
        float bb0 = __ldg(b2 + nq * 128 + lcol), bb1 = __ldg(b2 + nq * 128 + lcol + 1);
        int row0 = mw * 32 + mt * 16 + lr;
        *(__half2*)(sm + OF_A + swA(row0, lcol * 2)) =
            __floats2half2_rn(fmaxf(acc[mt][nt][0] + bb0, 0.f), fmaxf(acc[mt][nt][1] + bb1, 0.f));
        *(__half2*)(sm + OF_A + swA(row0 + 8, lcol * 2)) =
            __floats2half2_rn(fmaxf(acc[mt][nt][2] + bb0, 0.f), fmaxf(acc[mt][nt][3] + bb1, 0.f));
      }
  }
  for (int i = t; i < 64 * 24; i += NTH) ((float*)(sm + OF_SC))[i] = 0.f;
  __syncthreads();

  // ---- heads GEMM: warp = (mw strip) x (k-slice nw of 32), B frags via LDG ----
  {
    float hacc[2][3][4];
#pragma unroll
    for (int mt = 0; mt < 2; ++mt)
#pragma unroll
      for (int nt = 0; nt < 3; ++nt)
#pragma unroll
        for (int i = 0; i < 4; ++i) hacc[mt][nt][i] = 0.f;
    const uint4* hf = (const uint4*)((const char*)g_hd +
        (size_t)(((m * 4 + nq) * 4 + nw) * 4) * 512) + lane;
#pragma unroll
    for (int q = 0; q < 2; ++q) {
      uint4 h0 = hf[q * 64];         // n-tiles 0,1
      uint4 h1 = hf[q * 64 + 32];    // n-tiles 2,3 (tile 3 zero)
      int koff = nw * 32 + q * 16;
      uint32_t A0[4], A1[4];
      ldsm4(smb + OF_A + swA(mw * 32 + ag_r, (koff + ag_k) * 2), A0[0], A0[1], A0[2], A0[3]);
      ldsm4(smb + OF_A + swA(mw * 32 + 16 + ag_r, (koff + ag_k) * 2), A1[0], A1[1], A1[2], A1[3]);
      mma16816(hacc[0][0], A0[0], A0[1], A0[2], A0[3], h0.x, h0.y);
      mma16816(hacc[0][1], A0[0], A0[1], A0[2], A0[3], h0.z, h0.w);
      mma16816(hacc[0][2], A0[0], A0[1], A0[2], A0[3], h1.x, h1.y);
      mma16816(hacc[1][0], A1[0], A1[1], A1[2], A1[3], h0.x, h0.y);
      mma16816(hacc[1][1], A1[0], A1[1], A1[2], A1[3], h0.z, h0.w);
      mma16816(hacc[1][2], A1[0], A1[1], A1[2], A1[3], h1.x, h1.y);
    }
    float* sp = (float*)(sm + OF_SC);
#pragma unroll
    for (int mt = 0; mt < 2; ++mt)
#pragma unroll
      for (int nt = 0; nt < 3; ++nt) {
        int row0 = mw * 32 + mt * 16 + lr, col = nt * 8 + lc2;
        atomicAdd(sp + row0 * 24 + col,           hacc[mt][nt][0]);
        atomicAdd(sp + row0 * 24 + col + 1,       hacc[mt][nt][1]);
        atomicAdd(sp + (row0 + 8) * 24 + col,     hacc[mt][nt][2]);
        atomicAdd(sp + (row0 + 8) * 24 + col + 1, hacc[mt][nt][3]);
      }
  }
  __syncthreads();

  for (int i = t; i < 64 * 22; i += NTH) {
    int s = i / 22, c = i - s * 22;
    g_part[((size_t)(g * 4 + nq) * 32768 + s0 + s) * 22 + c] = ((float*)(sm + OF_SC))[s * 24 + c];
  }
}

__global__ void epilogue_kernel(PE p, int B) {
  int s = blockIdx.x * blockDim.x + threadIdx.x;
  if (s >= B) return;
  float hd[9][22];
#pragma unroll
  for (int q = 0; q < 9; ++q) {
#pragma unroll
    for (int c = 0; c < 22; ++c) hd[q][c] = 0.f;
#pragma unroll
    for (int nq = 0; nq < 4; ++nq) {
      const float* pp = g_part + ((size_t)(q * 4 + nq) * 32768 + s) * 22;
#pragma unroll
      for (int c = 0; c < 22; ++c) hd[q][c] += pp[c];
    }
  }
  float mx = -1e30f;
#pragma unroll
  for (int q = 3; q < 9; ++q) mx = fmaxf(mx, hd[q][21]);
  float den = 0.f, agg[21];
#pragma unroll
  for (int c = 0; c < 21; ++c) agg[c] = 0.f;
#pragma unroll
  for (int q = 3; q < 9; ++q) {
    float w = expf(hd[q][21] - mx);
    den += w;
#pragma unroll
    for (int c = 0; c < 21; ++c) agg[c] = fmaf(w, hd[q][c], agg[c]);
  }
  float inv = 1.f / den;

  float* o = p.out + (size_t)s * 105;
  float pos[4][3], coef[4][9], cov[4][9];
  for (int e = 0; e < 3; ++e) {
    for (int d = 0; d < 3; ++d) pos[e][d]  = hd[e][d] + p.ent_bpos[e * 3 + d];
    for (int c = 0; c < 9; ++c) coef[e][c] = hd[e][3 + c] + p.ent_bc[e * 9 + c];
    for (int c = 0; c < 9; ++c) cov[e][c]  = softplusf(hd[e][12 + c] + p.ent_bv[e * 9 + c]);
  }
  for (int d = 0; d < 3; ++d) pos[3][d]  = agg[d] * inv + p.b_bpos[d];
  for (int c = 0; c < 9; ++c) coef[3][c] = agg[3 + c] * inv + p.b_bc[c];
  for (int c = 0; c < 9; ++c) cov[3][c]  = softplusf(agg[12 + c] * inv + p.b_bv[c]);
  for (int i = 0; i < 4; ++i) {
    float x = pos[i][0], y = pos[i][1], z = pos[i][2];
    for (int c = 0; c < 9; ++c) o[i * 24 + c]     = coef[i][c];
    for (int c = 0; c < 9; ++c) o[i * 24 + 9 + c] = cov[i][c];
    o[i * 24 + 18] = (4096.f - x) * 1e-3f;
    o[i * 24 + 19] = (4096.f + x) * 1e-3f;
    o[i * 24 + 20] = (5120.f - y) * 1e-3f;
    o[i * 24 + 21] = (5120.f + y) * 1e-3f;
    o[i * 24 + 22] = z * 1e-3f;
    o[i * 24 + 23] = (2044.f - z) * 1e-3f;
  }
  const int iu[6] = {0, 0, 0, 1, 1, 2}, ju[6] = {1, 2, 3, 2, 3, 3};
  for (int q = 0; q < 6; ++q) {
    int i = iu[q], j = ju[q];
    float d2 = 0.f, cd = 0.f;
    for (int d = 0; d < 3; ++d) { float df = pos[i][d] - pos[j][d]; d2 = fmaf(df, df, d2); }
    for (int c = 0; c < 9; ++c) cd = fmaf(coef[i][c], coef[j][c], cd);
    o[96 + q] = expf(-2.f * d2) * cd;
  }
  for (int d = 0; d < 3; ++d) {
    float ga = p.gs_b[d];
    for (int k = 0; k < 10; ++k)
      ga = fmaf(p.tokens[(size_t)s * 100 + 90 + k], p.gs_W[k * 3 + d], ga);
    o[102 + d] = ga;
  }
}

extern "C" void kernel_launch(void* const* d_in, const int* in_sizes, int n_in,
                              void* d_out, int out_size) {
  pack_kernel<<<512, 256>>>(
      (const float*)d_in[3],  (const float*)d_in[13],
      (const float*)d_in[1],  (const float*)d_in[2],
      (const float*)d_in[11], (const float*)d_in[12],
      (const float*)d_in[5],  (const float*)d_in[7],  (const float*)d_in[9],
      (const float*)d_in[17], (const float*)d_in[19], (const float*)d_in[21],
      (const float*)d_in[15]);

  int B = in_sizes[0] / 100;

  PM pm;
  pm.tokens = (const float*)d_in[0];
  pm.ent_b2 = (const float*)d_in[4];
  pm.pad_b2 = (const float*)d_in[14];
  cudaFuncSetAttribute(spectral_mma_kernel, cudaFuncAttributeMaxDynamicSharedMemorySize, SMEM_SZ);
  dim3 grid(B / 64, 9, 4);
  spectral_mma_kernel<<<grid, NTH, SMEM_SZ>>>(pm);

  PE pe;
  pe.tokens = (const float*)d_in[0];
  pe.ent_bpos = (const float*)d_in[6];
  pe.ent_bc = (const float*)d_in[8];
  pe.ent_bv = (const float*)d_in[10];
  pe.b_bpos = (const float*)d_in[18];
  pe.b_bc = (const float*)d_in[20];
  pe.b_bv = (const float*)d_in[22];
  pe.gs_W = (const float*)d_in[23];
  pe.gs_b = (const float*)d_in[24];
  pe.out = (float*)d_out;
  epilogue_kernel<<<(B + 127) / 128, 128>>>(pe, B);
}

// round 12
// speedup vs baseline: 1.3493x; 1.1152x over previous
#include <cuda_runtime.h>
#include <cuda_fp16.h>
#include <math.h>
#include <stdint.h>

// ---------------- packed fp16 weights (all fragment-ordered for direct LDG) ----
// g_w2: [m4][nq4][kt32][nw4][grp2][lane32][4 halves]
// g_w1: [m4][w8][pq4][lane32][8 halves]   (k10 = b1 folded)
// g_hd: [m4][nq4][nw4][q2][tp2][lane32][4 halves]
__device__ __align__(16) __half g_w2[1048576];
__device__ __align__(16) __half g_w1[32768];
__device__ __align__(16) __half g_hd[65536];
// head sums: [g (9)][sample (32768)][22] f32, accumulated via atomicAdd
__device__ float g_part[9 * 32768 * 22];

struct PM {
  const float *tokens;
  const float *ent_b2, *pad_b2;
};
struct PE {
  const float *tokens;
  const float *ent_bpos, *ent_bc, *ent_bv;
  const float *b_bpos, *b_bc, *b_bv;
  const float *gs_W, *gs_b;
  float *out;
};

__global__ void pack_kernel(const float* eW2, const float* pW2,
                            const float* eW1, const float* eb1,
                            const float* pW1, const float* pb1,
                            const float* eWpos, const float* eWc, const float* eWv,
                            const float* bWpos, const float* bWc, const float* bWv,
                            const float* attnW) {
  int tid = blockIdx.x * blockDim.x + threadIdx.x;
  int NT = gridDim.x * blockDim.x;
  for (int idx = tid; idx < 9 * 32768 * 22; idx += NT) g_part[idx] = 0.f;
  for (int idx = tid; idx < 4 * 512 * 512; idx += NT) {
    int m = idx >> 18, r = idx & 262143, k = r >> 9, n = r & 511;
    float v = (m < 3) ? eW2[m * 262144 + k * 512 + n] : pW2[k * 512 + n];
    int nq = n >> 7, nl = n & 127;
    int nw = nl >> 5, nt = (nl >> 3) & 3;
    int grp = nt >> 1, odd = nt & 1;
    int kt = k >> 4, kk = k & 15;
    int lane = (nl & 7) * 4 + ((kk & 7) >> 1);
    int dst = ((((m * 4 + nq) * 32 + kt) * 4 + nw) * 2 + grp) * 256 +
              lane * 8 + odd * 4 + ((kk >> 3) & 1) * 2 + (kk & 1);
    g_w2[dst] = __float2half(v);
  }
  for (int idx = tid; idx < 4 * 512 * 16; idx += NT) {
    int m = idx >> 13, r = idx & 8191, n = r >> 4, k = r & 15;
    float v = 0.f;
    if (k < 10)       v = (m < 3) ? eW1[m * 5120 + k * 512 + n] : pW1[k * 512 + n];
    else if (k == 10) v = (m < 3) ? eb1[m * 512 + n] : pb1[n];
    int w = n >> 6, pq = (n >> 4) & 3, odd = (n >> 3) & 1;
    int lane = (n & 7) * 4 + ((k & 7) >> 1);
    int dst = ((m * 8 + w) * 4 + pq) * 256 + lane * 8 + odd * 4 + ((k >> 3) & 1) * 2 + (k & 1);
    g_w1[dst] = __float2half(v);
  }
  for (int idx = tid; idx < 4 * 32 * 512; idx += NT) {
    int m = idx >> 14, r = idx & 16383, n = r >> 9, k = r & 511;
    float v = 0.f;
    if (m < 3) {
      if (n < 3)       v = eWpos[m * 1536 + k * 3 + n];
      else if (n < 12) v = eWc[m * 4608 + k * 9 + (n - 3)];
      else if (n < 21) v = eWv[m * 4608 + k * 9 + (n - 12)];
    } else {
      if (n < 3)       v = bWpos[k * 3 + n];
      else if (n < 12) v = bWc[k * 9 + (n - 3)];
      else if (n < 21) v = bWv[k * 9 + (n - 12)];
      else if (n == 21) v = attnW[k];
    }
    int nq = k >> 7, kl = k & 127;
    int nw = kl >> 5, q = (kl >> 4) & 1, kk = kl & 15;
    int tp = n >> 4, odd = (n >> 3) & 1;
    int lane = (n & 7) * 4 + ((kk & 7) >> 1);
    int dst = ((((m * 4 + nq) * 4 + nw) * 2 + q) * 2 + tp) * 256 +
              lane * 8 + odd * 4 + ((kk >> 3) & 1) * 2 + (kk & 1);
    g_hd[dst] = __float2half(v);
  }
}

// ---------------- mma helpers ----------------
__device__ __forceinline__ void ldsm4(uint32_t a, uint32_t& r0, uint32_t& r1,
                                      uint32_t& r2, uint32_t& r3) {
  asm volatile("ldmatrix.sync.aligned.m8n8.x4.shared.b16 {%0,%1,%2,%3}, [%4];"
               : "=r"(r0), "=r"(r1), "=r"(r2), "=r"(r3) : "r"(a));
}
__device__ __forceinline__ void mma16816(float* c, uint32_t a0, uint32_t a1,
                                         uint32_t a2, uint32_t a3,
                                         uint32_t b0, uint32_t b1) {
  asm volatile(
      "mma.sync.aligned.m16n8k16.row.col.f32.f16.f16.f32 "
      "{%0,%1,%2,%3},{%4,%5,%6,%7},{%8,%9},{%0,%1,%2,%3};"
      : "+f"(c[0]), "+f"(c[1]), "+f"(c[2]), "+f"(c[3])
      : "r"(a0), "r"(a1), "r"(a2), "r"(a3), "r"(b0), "r"(b1));
}
__device__ __forceinline__ uint32_t packrelu(float a, float b) {
  __half2 h = __floats2half2_rn(fmaxf(a, 0.f), fmaxf(b, 0.f));
  return *(uint32_t*)&h;
}
__device__ __forceinline__ int swA(int row, int kbyte) {
  return (row * 1024 + kbyte) ^ ((row & 7) << 4);
}

// ---------------- smem layout ----------------
#define NTH 256
static constexpr int OF_A  = 0;        // h1 tile: 64 rows x 1024B swizzled = 65,536 (never overwritten)
static constexpr int OF_SC = 65536;    // x-tile 2,048
static constexpr int SMEM_SZ = 67584;  // 66 KB -> 3 CTAs/SM

__device__ __forceinline__ float softplusf(float x) { return (x > 20.f) ? x : log1pf(expf(x)); }

__global__ void __launch_bounds__(NTH, 3) spectral_mma_kernel(PM p) {
  extern __shared__ __align__(128) unsigned char sm[];
  const uint32_t smb = (uint32_t)__cvta_generic_to_shared(sm);
  const int t = threadIdx.x, wid = t >> 5, lane = t & 31;
  const int g = blockIdx.y, nh = blockIdx.z;
  const int m = (g < 3) ? g : 3;
  const int s0 = blockIdx.x * 64;
  const int mw = wid & 1, nw = wid >> 1;                // 2 M-warps x 4 N-warps (64x128)
  const int ag_r = ((lane >> 3) & 1) * 8 + (lane & 7);
  const int ag_k = ((lane >> 4) & 1) * 8;
  const int lr = lane >> 2, lc2 = (lane & 3) * 2;

  // ---- prologue: x-tile (64x16, ones at k=10) ----
  for (int i = t; i < 64 * 16; i += NTH) {
    int s = i >> 4, k = i & 15;
    float v = (k < 10) ? p.tokens[(size_t)(s0 + s) * 100 + g * 10 + k] : (k == 10 ? 1.f : 0.f);
    *(__half*)(sm + OF_SC + s * 32 + k * 2) = __float2half(v);
  }
  __syncthreads();

  // ---- phase A: h1 = relu(x @ W1T) -> swizzled A-tile; warp wid covers cols wid*64 ----
  {
    uint32_t xa[4][4];
#pragma unroll
    for (int mt = 0; mt < 4; ++mt)
      ldsm4(smb + OF_SC + (mt * 16 + ag_r) * 32 + ag_k * 2,
            xa[mt][0], xa[mt][1], xa[mt][2], xa[mt][3]);
    const uint4* w1f = (const uint4*)((const char*)g_w1 + (size_t)(m * 8 + wid) * 2048) + lane;
#pragma unroll
    for (int pq = 0; pq < 4; ++pq) {
      uint4 bf = w1f[pq * 32];
      float pa[4][2][4];
#pragma unroll
      for (int mt = 0; mt < 4; ++mt) {
#pragma unroll
        for (int tn = 0; tn < 2; ++tn)
#pragma unroll
          for (int i = 0; i < 4; ++i) pa[mt][tn][i] = 0.f;
        mma16816(pa[mt][0], xa[mt][0], xa[mt][1], xa[mt][2], xa[mt][3], bf.x, bf.y);
        mma16816(pa[mt][1], xa[mt][0], xa[mt][1], xa[mt][2], xa[mt][3], bf.z, bf.w);
      }
#pragma unroll
      for (int mt = 0; mt < 4; ++mt)
#pragma unroll
        for (int tn = 0; tn < 2; ++tn) {
          int col = wid * 64 + pq * 16 + tn * 8 + lc2;
          int row0 = mt * 16 + lr;
          *(__half2*)(sm + OF_A + swA(row0, col * 2)) =
              __floats2half2_rn(fmaxf(pa[mt][tn][0], 0.f), fmaxf(pa[mt][tn][1], 0.f));
          *(__half2*)(sm + OF_A + swA(row0 + 8, col * 2)) =
              __floats2half2_rn(fmaxf(pa[mt][tn][2], 0.f), fmaxf(pa[mt][tn][3], 0.f));
        }
    }
  }
  __syncthreads();   // h1 complete; A-tile read-only for the REST of the kernel

  const float* b2 = (g < 3) ? (p.ent_b2 + m * 512) : p.pad_b2;

  // ---- two nq quarters per CTA, barrier-free ----
  for (int sub = 0; sub < 2; ++sub) {
    const int nq = nh * 2 + sub;

    float acc[2][4][4];
#pragma unroll
    for (int mt = 0; mt < 2; ++mt)
#pragma unroll
      for (int nt = 0; nt < 4; ++nt)
#pragma unroll
        for (int i = 0; i < 4; ++i) acc[mt][nt][i] = 0.f;

    const char* wbase = (const char*)g_w2 +
        (size_t)(m * 4 + nq) * 131072 + nw * 1024 + lane * 16;
    uint4 bc0 = *(const uint4*)(wbase);
    uint4 bc1 = *(const uint4*)(wbase + 512);
#pragma unroll 4
    for (int kt = 0; kt < 32; ++kt) {
      uint4 bn0, bn1;
      if (kt < 31) {
        bn0 = *(const uint4*)(wbase + (kt + 1) * 4096);
        bn1 = *(const uint4*)(wbase + (kt + 1) * 4096 + 512);
      }
      uint32_t A0[4], A1[4];
      ldsm4(smb + OF_A + swA(mw * 32 + ag_r, (kt * 16 + ag_k) * 2), A0[0], A0[1], A0[2], A0[3]);
      ldsm4(smb + OF_A + swA(mw * 32 + 16 + ag_r, (kt * 16 + ag_k) * 2), A1[0], A1[1], A1[2], A1[3]);
      mma16816(acc[0][0], A0[0], A0[1], A0[2], A0[3], bc0.x, bc0.y);
      mma16816(acc[1][0], A1[0], A1[1], A1[2], A1[3], bc0.x, bc0.y);
      mma16816(acc[0][1], A0[0], A0[1], A0[2], A0[3], bc0.z, bc0.w);
      mma16816(acc[1][1], A1[0], A1[1], A1[2], A1[3], bc0.z, bc0.w);
      mma16816(acc[0][2], A0[0], A0[1], A0[2], A0[3], bc1.x, bc1.y);
      mma16816(acc[1][2], A1[0], A1[1], A1[2], A1[3], bc1.x, bc1.y);
      mma16816(acc[0][3], A0[0], A0[1], A0[2], A0[3], bc1.z, bc1.w);
      mma16816(acc[1][3], A1[0], A1[1], A1[2], A1[3], bc1.z, bc1.w);
      bc0 = bn0; bc1 = bn1;
    }

    // ---- h2 (bias+relu) -> A-frags IN REGISTERS (C-frag == A-frag identity) ----
    uint32_t afh[2][2][4];
#pragma unroll
    for (int q = 0; q < 2; ++q) {
      int ce = nq * 128 + nw * 32 + q * 16 + lc2;   // even tile cols; odd tile +8
      float be0 = __ldg(b2 + ce),     be1 = __ldg(b2 + ce + 1);
      float bo0 = __ldg(b2 + ce + 8), bo1 = __ldg(b2 + ce + 9);
#pragma unroll
      for (int mt = 0; mt < 2; ++mt) {
        afh[mt][q][0] = packrelu(acc[mt][2 * q][0] + be0, acc[mt][2 * q][1] + be1);
        afh[mt][q][1] = packrelu(acc[mt][2 * q][2] + be0, acc[mt][2 * q][3] + be1);
        afh[mt][q][2] = packrelu(acc[mt][2 * q + 1][0] + bo0, acc[mt][2 * q + 1][1] + bo1);
        afh[mt][q][3] = packrelu(acc[mt][2 * q + 1][2] + bo0, acc[mt][2 * q + 1][3] + bo1);
      }
    }

    // ---- heads GEMM from registers: k-slice nq*128 + nw*32 (+q*16) ----
    float hacc[2][3][4];
#pragma unroll
    for (int mt = 0; mt < 2; ++mt)
#pragma unroll
      for (int nt = 0; nt < 3; ++nt)
#pragma unroll
        for (int i = 0; i < 4; ++i) hacc[mt][nt][i] = 0.f;
    const uint4* hf = (const uint4*)((const char*)g_hd +
        (size_t)((m * 4 + nq) * 4 + nw) * 2048) + lane;
#pragma unroll
    for (int q = 0; q < 2; ++q) {
      uint4 h0 = hf[q * 64];
      uint4 h1 = hf[q * 64 + 32];
#pragma unroll
      for (int mt = 0; mt < 2; ++mt) {
        mma16816(hacc[mt][0], afh[mt][q][0], afh[mt][q][1], afh[mt][q][2], afh[mt][q][3], h0.x, h0.y);
        mma16816(hacc[mt][1], afh[mt][q][0], afh[mt][q][1], afh[mt][q][2], afh[mt][q][3], h0.z, h0.w);
        mma16816(hacc[mt][2], afh[mt][q][0], afh[mt][q][1], afh[mt][q][2], afh[mt][q][3], h1.x, h1.y);
      }
    }

    // ---- accumulate into g_part via global atomics (no SMEM, no syncs) ----
#pragma unroll
    for (int mt = 0; mt < 2; ++mt)
#pragma unroll
      for (int nt = 0; nt < 3; ++nt) {
        int col = nt * 8 + lc2;
        if (col < 22) {
          int row0 = mw * 32 + mt * 16 + lr;
          size_t b = ((size_t)g * 32768 + s0 + row0) * 22 + col;
          atomicAdd(&g_part[b],            hacc[mt][nt][0]);
          atomicAdd(&g_part[b + 1],        hacc[mt][nt][1]);
          atomicAdd(&g_part[b + 8 * 22],     hacc[mt][nt][2]);
          atomicAdd(&g_part[b + 8 * 22 + 1], hacc[mt][nt][3]);
        }
      }
  }
}

__global__ void epilogue_kernel(PE p, int B) {
  int s = blockIdx.x * blockDim.x + threadIdx.x;
  if (s >= B) return;
  float hd[9][22];
#pragma unroll
  for (int q = 0; q < 9; ++q) {
    const float* pp = g_part + ((size_t)q * 32768 + s) * 22;
#pragma unroll
    for (int c = 0; c < 22; ++c) hd[q][c] = pp[c];
  }
  float mx = -1e30f;
#pragma unroll
  for (int q = 3; q < 9; ++q) mx = fmaxf(mx, hd[q][21]);
  float den = 0.f, agg[21];
#pragma unroll
  for (int c = 0; c < 21; ++c) agg[c] = 0.f;
#pragma unroll
  for (int q = 3; q < 9; ++q) {
    float w = expf(hd[q][21] - mx);
    den += w;
#pragma unroll
    for (int c = 0; c < 21; ++c) agg[c] = fmaf(w, hd[q][c], agg[c]);
  }
  float inv = 1.f / den;

  float* o = p.out + (size_t)s * 105;
  float pos[4][3], coef[4][9], cov[4][9];
  for (int e = 0; e < 3; ++e) {
    for (int d = 0; d < 3; ++d) pos[e][d]  = hd[e][d] + p.ent_bpos[e * 3 + d];
    for (int c = 0; c < 9; ++c) coef[e][c] = hd[e][3 + c] + p.ent_bc[e * 9 + c];
    for (int c = 0; c < 9; ++c) cov[e][c]  = softplusf(hd[e][12 + c] + p.ent_bv[e * 9 + c]);
  }
  for (int d = 0; d < 3; ++d) pos[3][d]  = agg[d] * inv + p.b_bpos[d];
  for (int c = 0; c < 9; ++c) coef[3][c] = agg[3 + c] * inv + p.b_bc[c];
  for (int c = 0; c < 9; ++c) cov[3][c]  = softplusf(agg[12 + c] * inv + p.b_bv[c]);
  for (int i = 0; i < 4; ++i) {
    float x = pos[i][0], y = pos[i][1], z = pos[i][2];
    for (int c = 0; c < 9; ++c) o[i * 24 + c]     = coef[i][c];
    for (int c = 0; c < 9; ++c) o[i * 24 + 9 + c] = cov[i][c];
    o[i * 24 + 18] = (4096.f - x) * 1e-3f;
    o[i * 24 + 19] = (4096.f + x) * 1e-3f;
    o[i * 24 + 20] = (5120.f - y) * 1e-3f;
    o[i * 24 + 21] = (5120.f + y) * 1e-3f;
    o[i * 24 + 22] = z * 1e-3f;
    o[i * 24 + 23] = (2044.f - z) * 1e-3f;
  }
  const int iu[6] = {0, 0, 0, 1, 1, 2}, ju[6] = {1, 2, 3, 2, 3, 3};
  for (int q = 0; q < 6; ++q) {
    int i = iu[q], j = ju[q];
    float d2 = 0.f, cd = 0.f;
    for (int d = 0; d < 3; ++d) { float df = pos[i][d] - pos[j][d]; d2 = fmaf(df, df, d2); }
    for (int c = 0; c < 9; ++c) cd = fmaf(coef[i][c], coef[j][c], cd);
    o[96 + q] = expf(-2.f * d2) * cd;
  }
  for (int d = 0; d < 3; ++d) {
    float ga = p.gs_b[d];
    for (int k = 0; k < 10; ++k)
      ga = fmaf(p.tokens[(size_t)s * 100 + 90 + k], p.gs_W[k * 3 + d], ga);
    o[102 + d] = ga;
  }
}

extern "C" void kernel_launch(void* const* d_in, const int* in_sizes, int n_in,
                              void* d_out, int out_size) {
  pack_kernel<<<512, 256>>>(
      (const float*)d_in[3],  (const float*)d_in[13],
      (const float*)d_in[1],  (const float*)d_in[2],
      (const float*)d_in[11], (const float*)d_in[12],
      (const float*)d_in[5],  (const float*)d_in[7],  (const float*)d_in[9],
      (const float*)d_in[17], (const float*)d_in[19], (const float*)d_in[21],
      (const float*)d_in[15]);

  int B = in_sizes[0] / 100;

  PM pm;
  pm.tokens = (const float*)d_in[0];
  pm.ent_b2 = (const float*)d_in[4];
  pm.pad_b2 = (const float*)d_in[14];
  cudaFuncSetAttribute(spectral_mma_kernel, cudaFuncAttributeMaxDynamicSharedMemorySize, SMEM_SZ);
  dim3 grid(B / 64, 9, 2);
  spectral_mma_kernel<<<grid, NTH, SMEM_SZ>>>(pm);

  PE pe;
  pe.tokens = (const float*)d_in[0];
  pe.ent_bpos = (const float*)d_in[6];
  pe.ent_bc = (const float*)d_in[8];
  pe.ent_bv = (const float*)d_in[10];
  pe.b_bpos = (const float*)d_in[18];
  pe.b_bc = (const float*)d_in[20];
  pe.b_bv = (const float*)d_in[22];
  pe.gs_W = (const float*)d_in[23];
  pe.gs_b = (const float*)d_in[24];
  pe.out = (float*)d_out;
  epilogue_kernel<<<(B + 127) / 128, 128>>>(pe, B);
}

// round 13
// speedup vs baseline: 1.4251x; 1.0562x over previous
#include <cuda_runtime.h>
#include <cuda_fp16.h>
#include <math.h>
#include <stdint.h>

// ---------------- packed fp16 weights (all fragment-ordered for direct LDG) ----
// g_w2: [m4][nq4][kt32][nw4][grp2][lane32][4 halves]
// g_w1: [m4][w8][pq4][lane32][8 halves]   (k10 = b1 folded)
// g_hd: [m4][nq4][nw4][q2][tp2][lane32][4 halves]
__device__ __align__(16) __half g_w2[1048576];
__device__ __align__(16) __half g_w1[32768];
__device__ __align__(16) __half g_hd[65536];
// head sums: [g (9)][sample (32768)][22] f32, accumulated via atomicAdd
__device__ float g_part[9 * 32768 * 22];

struct PM {
  const float *tokens;
  const float *ent_b2, *pad_b2;
};
struct PE {
  const float *tokens;
  const float *ent_bpos, *ent_bc, *ent_bv;
  const float *b_bpos, *b_bc, *b_bv;
  const float *gs_W, *gs_b;
  float *out;
};

__global__ void pack_kernel(const float* eW2, const float* pW2,
                            const float* eW1, const float* eb1,
                            const float* pW1, const float* pb1,
                            const float* eWpos, const float* eWc, const float* eWv,
                            const float* bWpos, const float* bWc, const float* bWv,
                            const float* attnW) {
  int tid = blockIdx.x * blockDim.x + threadIdx.x;
  int NT = gridDim.x * blockDim.x;
  for (int idx = tid; idx < 9 * 32768 * 22; idx += NT) g_part[idx] = 0.f;
  for (int idx = tid; idx < 4 * 512 * 512; idx += NT) {
    int m = idx >> 18, r = idx & 262143, k = r >> 9, n = r & 511;
    float v = (m < 3) ? eW2[m * 262144 + k * 512 + n] : pW2[k * 512 + n];
    int nq = n >> 7, nl = n & 127;
    int nw = nl >> 5, nt = (nl >> 3) & 3;
    int grp = nt >> 1, odd = nt & 1;
    int kt = k >> 4, kk = k & 15;
    int lane = (nl & 7) * 4 + ((kk & 7) >> 1);
    int dst = ((((m * 4 + nq) * 32 + kt) * 4 + nw) * 2 + grp) * 256 +
              lane * 8 + odd * 4 + ((kk >> 3) & 1) * 2 + (kk & 1);
    g_w2[dst] = __float2half(v);
  }
  for (int idx = tid; idx < 4 * 512 * 16; idx += NT) {
    int m = idx >> 13, r = idx & 8191, n = r >> 4, k = r & 15;
    float v = 0.f;
    if (k < 10)       v = (m < 3) ? eW1[m * 5120 + k * 512 + n] : pW1[k * 512 + n];
    else if (k == 10) v = (m < 3) ? eb1[m * 512 + n] : pb1[n];
    int w = n >> 6, pq = (n >> 4) & 3, odd = (n >> 3) & 1;
    int lane = (n & 7) * 4 + ((k & 7) >> 1);
    int dst = ((m * 8 + w) * 4 + pq) * 256 + lane * 8 + odd * 4 + ((k >> 3) & 1) * 2 + (k & 1);
    g_w1[dst] = __float2half(v);
  }
  for (int idx = tid; idx < 4 * 32 * 512; idx += NT) {
    int m = idx >> 14, r = idx & 16383, n = r >> 9, k = r & 511;
    float v = 0.f;
    if (m < 3) {
      if (n < 3)       v = eWpos[m * 1536 + k * 3 + n];
      else if (n < 12) v = eWc[m * 4608 + k * 9 + (n - 3)];
      else if (n < 21) v = eWv[m * 4608 + k * 9 + (n - 12)];
    } else {
      if (n < 3)       v = bWpos[k * 3 + n];
      else if (n < 12) v = bWc[k * 9 + (n - 3)];
      else if (n < 21) v = bWv[k * 9 + (n - 12)];
      else if (n == 21) v = attnW[k];
    }
    int nq = k >> 7, kl = k & 127;
    int nw = kl >> 5, q = (kl >> 4) & 1, kk = kl & 15;
    int tp = n >> 4, odd = (n >> 3) & 1;
    int lane = (n & 7) * 4 + ((kk & 7) >> 1);
    int dst = ((((m * 4 + nq) * 4 + nw) * 2 + q) * 2 + tp) * 256 +
              lane * 8 + odd * 4 + ((kk >> 3) & 1) * 2 + (kk & 1);
    g_hd[dst] = __float2half(v);
  }
}

// ---------------- mma helpers ----------------
__device__ __forceinline__ void ldsm4(uint32_t a, uint32_t& r0, uint32_t& r1,
                                      uint32_t& r2, uint32_t& r3) {
  asm volatile("ldmatrix.sync.aligned.m8n8.x4.shared.b16 {%0,%1,%2,%3}, [%4];"
               : "=r"(r0), "=r"(r1), "=r"(r2), "=r"(r3) : "r"(a));
}
__device__ __forceinline__ void mma16816(float* c, uint32_t a0, uint32_t a1,
                                         uint32_t a2, uint32_t a3,
                                         uint32_t b0, uint32_t b1) {
  asm volatile(
      "mma.sync.aligned.m16n8k16.row.col.f32.f16.f16.f32 "
      "{%0,%1,%2,%3},{%4,%5,%6,%7},{%8,%9},{%0,%1,%2,%3};"
      : "+f"(c[0]), "+f"(c[1]), "+f"(c[2]), "+f"(c[3])
      : "r"(a0), "r"(a1), "r"(a2), "r"(a3), "r"(b0), "r"(b1));
}
__device__ __forceinline__ uint32_t packrelu(float a, float b) {
  __half2 h = __floats2half2_rn(fmaxf(a, 0.f), fmaxf(b, 0.f));
  return *(uint32_t*)&h;
}
__device__ __forceinline__ int swA(int row, int kbyte) {
  return (row * 1024 + kbyte) ^ ((row & 7) << 4);
}

// ---------------- smem layout ----------------
#define NTH 256
static constexpr int OF_A  = 0;        // h1 tile: 64 rows x 1024B swizzled = 65,536 (never overwritten)
static constexpr int OF_SC = 65536;    // x-tile 2,048
static constexpr int SMEM_SZ = 67584;  // 66 KB -> 3 CTAs/SM

__device__ __forceinline__ float softplusf(float x) { return (x > 20.f) ? x : log1pf(expf(x)); }

__global__ void __launch_bounds__(NTH, 3) spectral_mma_kernel(PM p) {
  extern __shared__ __align__(128) unsigned char sm[];
  const uint32_t smb = (uint32_t)__cvta_generic_to_shared(sm);
  const int t = threadIdx.x, wid = t >> 5, lane = t & 31;
  const int g = blockIdx.y;
  const int m = (g < 3) ? g : 3;
  const int s0 = blockIdx.x * 64;
  const int mw = wid & 1, nw = wid >> 1;                // 2 M-warps x 4 N-warps (64x128)
  const int ag_r = ((lane >> 3) & 1) * 8 + (lane & 7);
  const int ag_k = ((lane >> 4) & 1) * 8;
  const int lr = lane >> 2, lc2 = (lane & 3) * 2;

  // ---- prologue: x-tile (64x16, ones at k=10) ----
  for (int i = t; i < 64 * 16; i += NTH) {
    int s = i >> 4, k = i & 15;
    float v = (k < 10) ? p.tokens[(size_t)(s0 + s) * 100 + g * 10 + k] : (k == 10 ? 1.f : 0.f);
    *(__half*)(sm + OF_SC + s * 32 + k * 2) = __float2half(v);
  }
  __syncthreads();

  // ---- phase A: h1 = relu(x @ W1T) -> swizzled A-tile; warp wid covers cols wid*64 ----
  {
    uint32_t xa[4][4];
#pragma unroll
    for (int mt = 0; mt < 4; ++mt)
      ldsm4(smb + OF_SC + (mt * 16 + ag_r) * 32 + ag_k * 2,
            xa[mt][0], xa[mt][1], xa[mt][2], xa[mt][3]);
    const uint4* w1f = (const uint4*)((const char*)g_w1 + (size_t)(m * 8 + wid) * 2048) + lane;
#pragma unroll
    for (int pq = 0; pq < 4; ++pq) {
      uint4 bf = w1f[pq * 32];
      float pa[4][2][4];
#pragma unroll
      for (int mt = 0; mt < 4; ++mt) {
#pragma unroll
        for (int tn = 0; tn < 2; ++tn)
#pragma unroll
          for (int i = 0; i < 4; ++i) pa[mt][tn][i] = 0.f;
        mma16816(pa[mt][0], xa[mt][0], xa[mt][1], xa[mt][2], xa[mt][3], bf.x, bf.y);
        mma16816(pa[mt][1], xa[mt][0], xa[mt][1], xa[mt][2], xa[mt][3], bf.z, bf.w);
      }
#pragma unroll
      for (int mt = 0; mt < 4; ++mt)
#pragma unroll
        for (int tn = 0; tn < 2; ++tn) {
          int col = wid * 64 + pq * 16 + tn * 8 + lc2;
          int row0 = mt * 16 + lr;
          *(__half2*)(sm + OF_A + swA(row0, col * 2)) =
              __floats2half2_rn(fmaxf(pa[mt][tn][0], 0.f), fmaxf(pa[mt][tn][1], 0.f));
          *(__half2*)(sm + OF_A + swA(row0 + 8, col * 2)) =
              __floats2half2_rn(fmaxf(pa[mt][tn][2], 0.f), fmaxf(pa[mt][tn][3], 0.f));
        }
    }
  }
  __syncthreads();   // h1 complete; A-tile read-only for the REST of the kernel

  const float* b2 = (g < 3) ? (p.ent_b2 + m * 512) : p.pad_b2;

  // ---- all four nq quarters in one CTA, barrier-free ----
  for (int nq = 0; nq < 4; ++nq) {
    float acc[2][4][4];
#pragma unroll
    for (int mt = 0; mt < 2; ++mt)
#pragma unroll
      for (int nt = 0; nt < 4; ++nt)
#pragma unroll
        for (int i = 0; i < 4; ++i) acc[mt][nt][i] = 0.f;

    const char* wbase = (const char*)g_w2 +
        (size_t)(m * 4 + nq) * 131072 + nw * 1024 + lane * 16;
    uint4 bc0 = *(const uint4*)(wbase);
    uint4 bc1 = *(const uint4*)(wbase + 512);
#pragma unroll 4
    for (int kt = 0; kt < 32; ++kt) {
      uint4 bn0, bn1;
      if (kt < 31) {
        bn0 = *(const uint4*)(wbase + (kt + 1) * 4096);
        bn1 = *(const uint4*)(wbase + (kt + 1) * 4096 + 512);
      }
      uint32_t A0[4], A1[4];
      ldsm4(smb + OF_A + swA(mw * 32 + ag_r, (kt * 16 + ag_k) * 2), A0[0], A0[1], A0[2], A0[3]);
      ldsm4(smb + OF_A + swA(mw * 32 + 16 + ag_r, (kt * 16 + ag_k) * 2), A1[0], A1[1], A1[2], A1[3]);
      mma16816(acc[0][0], A0[0], A0[1], A0[2], A0[3], bc0.x, bc0.y);
      mma16816(acc[1][0], A1[0], A1[1], A1[2], A1[3], bc0.x, bc0.y);
      mma16816(acc[0][1], A0[0], A0[1], A0[2], A0[3], bc0.z, bc0.w);
      mma16816(acc[1][1], A1[0], A1[1], A1[2], A1[3], bc0.z, bc0.w);
      mma16816(acc[0][2], A0[0], A0[1], A0[2], A0[3], bc1.x, bc1.y);
      mma16816(acc[1][2], A1[0], A1[1], A1[2], A1[3], bc1.x, bc1.y);
      mma16816(acc[0][3], A0[0], A0[1], A0[2], A0[3], bc1.z, bc1.w);
      mma16816(acc[1][3], A1[0], A1[1], A1[2], A1[3], bc1.z, bc1.w);
      bc0 = bn0; bc1 = bn1;
    }

    // ---- h2 (bias+relu) -> A-frags IN REGISTERS (C-frag == A-frag identity) ----
    uint32_t afh[2][2][4];
#pragma unroll
    for (int q = 0; q < 2; ++q) {
      int ce = nq * 128 + nw * 32 + q * 16 + lc2;   // even tile cols; odd tile +8
      float be0 = __ldg(b2 + ce),     be1 = __ldg(b2 + ce + 1);
      float bo0 = __ldg(b2 + ce + 8), bo1 = __ldg(b2 + ce + 9);
#pragma unroll
      for (int mt = 0; mt < 2; ++mt) {
        afh[mt][q][0] = packrelu(acc[mt][2 * q][0] + be0, acc[mt][2 * q][1] + be1);
        afh[mt][q][1] = packrelu(acc[mt][2 * q][2] + be0, acc[mt][2 * q][3] + be1);
        afh[mt][q][2] = packrelu(acc[mt][2 * q + 1][0] + bo0, acc[mt][2 * q + 1][1] + bo1);
        afh[mt][q][3] = packrelu(acc[mt][2 * q + 1][2] + bo0, acc[mt][2 * q + 1][3] + bo1);
      }
    }

    // ---- heads GEMM from registers: k-slice nq*128 + nw*32 (+q*16) ----
    float hacc[2][3][4];
#pragma unroll
    for (int mt = 0; mt < 2; ++mt)
#pragma unroll
      for (int nt = 0; nt < 3; ++nt)
#pragma unroll
        for (int i = 0; i < 4; ++i) hacc[mt][nt][i] = 0.f;
    const uint4* hf = (const uint4*)((const char*)g_hd +
        (size_t)((m * 4 + nq) * 4 + nw) * 2048) + lane;
#pragma unroll
    for (int q = 0; q < 2; ++q) {
      uint4 h0 = hf[q * 64];
      uint4 h1 = hf[q * 64 + 32];
#pragma unroll
      for (int mt = 0; mt < 2; ++mt) {
        mma16816(hacc[mt][0], afh[mt][q][0], afh[mt][q][1], afh[mt][q][2], afh[mt][q][3], h0.x, h0.y);
        mma16816(hacc[mt][1], afh[mt][q][0], afh[mt][q][1], afh[mt][q][2], afh[mt][q][3], h0.z, h0.w);
        mma16816(hacc[mt][2], afh[mt][q][0], afh[mt][q][1], afh[mt][q][2], afh[mt][q][3], h1.x, h1.y);
      }
    }

    // ---- accumulate into g_part via global atomics (no SMEM, no syncs) ----
#pragma unroll
    for (int mt = 0; mt < 2; ++mt)
#pragma unroll
      for (int nt = 0; nt < 3; ++nt) {
        int col = nt * 8 + lc2;
        if (col < 22) {
          int row0 = mw * 32 + mt * 16 + lr;
          size_t b = ((size_t)g * 32768 + s0 + row0) * 22 + col;
          atomicAdd(&g_part[b],              hacc[mt][nt][0]);
          atomicAdd(&g_part[b + 1],          hacc[mt][nt][1]);
          atomicAdd(&g_part[b + 8 * 22],     hacc[mt][nt][2]);
          atomicAdd(&g_part[b + 8 * 22 + 1], hacc[mt][nt][3]);
        }
      }
  }
}

__global__ void epilogue_kernel(PE p, int B) {
  int s = blockIdx.x * blockDim.x + threadIdx.x;
  if (s >= B) return;
  float hd[9][22];
#pragma unroll
  for (int q = 0; q < 9; ++q) {
    const float* pp = g_part + ((size_t)q * 32768 + s) * 22;
#pragma unroll
    for (int c = 0; c < 22; ++c) hd[q][c] = pp[c];
  }
  float mx = -1e30f;
#pragma unroll
  for (int q = 3; q < 9; ++q) mx = fmaxf(mx, hd[q][21]);
  float den = 0.f, agg[21];
#pragma unroll
  for (int c = 0; c < 21; ++c) agg[c] = 0.f;
#pragma unroll
  for (int q = 3; q < 9; ++q) {
    float w = expf(hd[q][21] - mx);
    den += w;
#pragma unroll
    for (int c = 0; c < 21; ++c) agg[c] = fmaf(w, hd[q][c], agg[c]);
  }
  float inv = 1.f / den;

  float* o = p.out + (size_t)s * 105;
  float pos[4][3], coef[4][9], cov[4][9];
  for (int e = 0; e < 3; ++e) {
    for (int d = 0; d < 3; ++d) pos[e][d]  = hd[e][d] + p.ent_bpos[e * 3 + d];
    for (int c = 0; c < 9; ++c) coef[e][c] = hd[e][3 + c] + p.ent_bc[e * 9 + c];
    for (int c = 0; c < 9; ++c) cov[e][c]  = softplusf(hd[e][12 + c] + p.ent_bv[e * 9 + c]);
  }
  for (int d = 0; d < 3; ++d) pos[3][d]  = agg[d] * inv + p.b_bpos[d];
  for (int c = 0; c < 9; ++c) coef[3][c] = agg[3 + c] * inv + p.b_bc[c];
  for (int c = 0; c < 9; ++c) cov[3][c]  = softplusf(agg[12 + c] * inv + p.b_bv[c]);
  for (int i = 0; i < 4; ++i) {
    float x = pos[i][0], y = pos[i][1], z = pos[i][2];
    for (int c = 0; c < 9; ++c) o[i * 24 + c]     = coef[i][c];
    for (int c = 0; c < 9; ++c) o[i * 24 + 9 + c] = cov[i][c];
    o[i * 24 + 18] = (4096.f - x) * 1e-3f;
    o[i * 24 + 19] = (4096.f + x) * 1e-3f;
    o[i * 24 + 20] = (5120.f - y) * 1e-3f;
    o[i * 24 + 21] = (5120.f + y) * 1e-3f;
    o[i * 24 + 22] = z * 1e-3f;
    o[i * 24 + 23] = (2044.f - z) * 1e-3f;
  }
  const int iu[6] = {0, 0, 0, 1, 1, 2}, ju[6] = {1, 2, 3, 2, 3, 3};
  for (int q = 0; q < 6; ++q) {
    int i = iu[q], j = ju[q];
    float d2 = 0.f, cd = 0.f;
    for (int d = 0; d < 3; ++d) { float df = pos[i][d] - pos[j][d]; d2 = fmaf(df, df, d2); }
    for (int c = 0; c < 9; ++c) cd = fmaf(coef[i][c], coef[j][c], cd);
    o[96 + q] = expf(-2.f * d2) * cd;
  }
  for (int d = 0; d < 3; ++d) {
    float ga = p.gs_b[d];
    for (int k = 0; k < 10; ++k)
      ga = fmaf(p.tokens[(size_t)s * 100 + 90 + k], p.gs_W[k * 3 + d], ga);
    o[102 + d] = ga;
  }
}

extern "C" void kernel_launch(void* const* d_in, const int* in_sizes, int n_in,
                              void* d_out, int out_size) {
  pack_kernel<<<512, 256>>>(
      (const float*)d_in[3],  (const float*)d_in[13],
      (const float*)d_in[1],  (const float*)d_in[2],
      (const float*)d_in[11], (const float*)d_in[12],
      (const float*)d_in[5],  (const float*)d_in[7],  (const float*)d_in[9],
      (const float*)d_in[17], (const float*)d_in[19], (const float*)d_in[21],
      (const float*)d_in[15]);

  int B = in_sizes[0] / 100;

  PM pm;
  pm.tokens = (const float*)d_in[0];
  pm.ent_b2 = (const float*)d_in[4];
  pm.pad_b2 = (const float*)d_in[14];
  cudaFuncSetAttribute(spectral_mma_kernel, cudaFuncAttributeMaxDynamicSharedMemorySize, SMEM_SZ);
  dim3 grid(B / 64, 9, 1);
  spectral_mma_kernel<<<grid, NTH, SMEM_SZ>>>(pm);

  PE pe;
  pe.tokens = (const float*)d_in[0];
  pe.ent_bpos = (const float*)d_in[6];
  pe.ent_bc = (const float*)d_in[8];
  pe.ent_bv = (const float*)d_in[10];
  pe.b_bpos = (const float*)d_in[18];
  pe.b_bc = (const float*)d_in[20];
  pe.b_bv = (const float*)d_in[22];
  pe.gs_W = (const float*)d_in[23];
  pe.gs_b = (const float*)d_in[24];
  pe.out = (float*)d_out;
  epilogue_kernel<<<(B + 127) / 128, 128>>>(pe, B);
}

// round 14
// speedup vs baseline: 1.4267x; 1.0011x over previous
#include <cuda_runtime.h>
#include <cuda_fp16.h>
#include <math.h>
#include <stdint.h>

// ---------------- packed fp16 weights (all fragment-ordered for direct LDG) ----
// g_w2: [m4][nq4][kt32][nw4][grp2][lane32][4 halves]
// g_w1: [m4][w8][pq4][lane32][8 halves]   (k10 = b1 folded)
// g_hd: [m4][nq4][nw4][q2][tp2][lane32][4 halves]
__device__ __align__(16) __half g_w2[1048576];
__device__ __align__(16) __half g_w1[32768];
__device__ __align__(16) __half g_hd[65536];
// head sums: [g (9)][sample (32768)][22] f32, accumulated via atomicAdd
__device__ float g_part[9 * 32768 * 22];

struct PM {
  const float *tokens;
  const float *ent_b2, *pad_b2;
};
struct PE {
  const float *tokens;
  const float *ent_bpos, *ent_bc, *ent_bv;
  const float *b_bpos, *b_bc, *b_bv;
  const float *gs_W, *gs_b;
  float *out;
};

__global__ void pack_kernel(const float* eW2, const float* pW2,
                            const float* eW1, const float* eb1,
                            const float* pW1, const float* pb1,
                            const float* eWpos, const float* eWc, const float* eWv,
                            const float* bWpos, const float* bWc, const float* bWv,
                            const float* attnW) {
  int tid = blockIdx.x * blockDim.x + threadIdx.x;
  int NT = gridDim.x * blockDim.x;
  for (int idx = tid; idx < 9 * 32768 * 22; idx += NT) g_part[idx] = 0.f;
  for (int idx = tid; idx < 4 * 512 * 512; idx += NT) {
    int m = idx >> 18, r = idx & 262143, k = r >> 9, n = r & 511;
    float v = (m < 3) ? eW2[m * 262144 + k * 512 + n] : pW2[k * 512 + n];
    int nq = n >> 7, nl = n & 127;
    int nw = nl >> 5, nt = (nl >> 3) & 3;
    int grp = nt >> 1, odd = nt & 1;
    int kt = k >> 4, kk = k & 15;
    int lane = (nl & 7) * 4 + ((kk & 7) >> 1);
    int dst = ((((m * 4 + nq) * 32 + kt) * 4 + nw) * 2 + grp) * 256 +
              lane * 8 + odd * 4 + ((kk >> 3) & 1) * 2 + (kk & 1);
    g_w2[dst] = __float2half(v);
  }
  for (int idx = tid; idx < 4 * 512 * 16; idx += NT) {
    int m = idx >> 13, r = idx & 8191, n = r >> 4, k = r & 15;
    float v = 0.f;
    if (k < 10)       v = (m < 3) ? eW1[m * 5120 + k * 512 + n] : pW1[k * 512 + n];
    else if (k == 10) v = (m < 3) ? eb1[m * 512 + n] : pb1[n];
    int w = n >> 6, pq = (n >> 4) & 3, odd = (n >> 3) & 1;
    int lane = (n & 7) * 4 + ((k & 7) >> 1);
    int dst = ((m * 8 + w) * 4 + pq) * 256 + lane * 8 + odd * 4 + ((k >> 3) & 1) * 2 + (k & 1);
    g_w1[dst] = __float2half(v);
  }
  for (int idx = tid; idx < 4 * 32 * 512; idx += NT) {
    int m = idx >> 14, r = idx & 16383, n = r >> 9, k = r & 511;
    float v = 0.f;
    if (m < 3) {
      if (n < 3)       v = eWpos[m * 1536 + k * 3 + n];
      else if (n < 12) v = eWc[m * 4608 + k * 9 + (n - 3)];
      else if (n < 21) v = eWv[m * 4608 + k * 9 + (n - 12)];
    } else {
      if (n < 3)       v = bWpos[k * 3 + n];
      else if (n < 12) v = bWc[k * 9 + (n - 3)];
      else if (n < 21) v = bWv[k * 9 + (n - 12)];
      else if (n == 21) v = attnW[k];
    }
    int nq = k >> 7, kl = k & 127;
    int nw = kl >> 5, q = (kl >> 4) & 1, kk = kl & 15;
    int tp = n >> 4, odd = (n >> 3) & 1;
    int lane = (n & 7) * 4 + ((kk & 7) >> 1);
    int dst = ((((m * 4 + nq) * 4 + nw) * 2 + q) * 2 + tp) * 256 +
              lane * 8 + odd * 4 + ((kk >> 3) & 1) * 2 + (kk & 1);
    g_hd[dst] = __float2half(v);
  }
}

// ---------------- mma helpers ----------------
__device__ __forceinline__ void ldsm4(uint32_t a, uint32_t& r0, uint32_t& r1,
                                      uint32_t& r2, uint32_t& r3) {
  asm volatile("ldmatrix.sync.aligned.m8n8.x4.shared.b16 {%0,%1,%2,%3}, [%4];"
               : "=r"(r0), "=r"(r1), "=r"(r2), "=r"(r3) : "r"(a));
}
__device__ __forceinline__ void mma16816(float* c, uint32_t a0, uint32_t a1,
                                         uint32_t a2, uint32_t a3,
                                         uint32_t b0, uint32_t b1) {
  asm volatile(
      "mma.sync.aligned.m16n8k16.row.col.f32.f16.f16.f32 "
      "{%0,%1,%2,%3},{%4,%5,%6,%7},{%8,%9},{%0,%1,%2,%3};"
      : "+f"(c[0]), "+f"(c[1]), "+f"(c[2]), "+f"(c[3])
      : "r"(a0), "r"(a1), "r"(a2), "r"(a3), "r"(b0), "r"(b1));
}
__device__ __forceinline__ uint32_t packrelu(float a, float b) {
  __half2 h = __floats2half2_rn(fmaxf(a, 0.f), fmaxf(b, 0.f));
  return *(uint32_t*)&h;
}
__device__ __forceinline__ int swA(int row, int kbyte) {
  return (row * 1024 + kbyte) ^ ((row & 7) << 4);
}

// ---------------- smem layout ----------------
#define NTH 256
static constexpr int OF_A  = 0;        // h1 tile: 64 rows x 1024B swizzled = 65,536 (never overwritten)
static constexpr int OF_SC = 65536;    // x-tile 2,048
static constexpr int SMEM_SZ = 67584;  // 66 KB -> 3 CTAs/SM

__device__ __forceinline__ float softplusf(float x) { return (x > 20.f) ? x : log1pf(expf(x)); }

__global__ void __launch_bounds__(NTH, 3) spectral_mma_kernel(PM p) {
  extern __shared__ __align__(128) unsigned char sm[];
  const uint32_t smb = (uint32_t)__cvta_generic_to_shared(sm);
  const int t = threadIdx.x, wid = t >> 5, lane = t & 31;
  const int g = blockIdx.y;
  const int m = (g < 3) ? g : 3;
  const int s0 = blockIdx.x * 64;
  const int mw = wid & 1, nw = wid >> 1;                // 2 M-warps x 4 N-warps (64x128)
  const int ag_r = ((lane >> 3) & 1) * 8 + (lane & 7);
  const int ag_k = ((lane >> 4) & 1) * 8;
  const int lr = lane >> 2, lc2 = (lane & 3) * 2;

  // ---- prologue: x-tile (64x16, ones at k=10) ----
  for (int i = t; i < 64 * 16; i += NTH) {
    int s = i >> 4, k = i & 15;
    float v = (k < 10) ? p.tokens[(size_t)(s0 + s) * 100 + g * 10 + k] : (k == 10 ? 1.f : 0.f);
    *(__half*)(sm + OF_SC + s * 32 + k * 2) = __float2half(v);
  }
  __syncthreads();

  // ---- phase A: h1 = relu(x @ W1T) -> swizzled A-tile; warp wid covers cols wid*64 ----
  {
    uint32_t xa[4][4];
#pragma unroll
    for (int mt = 0; mt < 4; ++mt)
      ldsm4(smb + OF_SC + (mt * 16 + ag_r) * 32 + ag_k * 2,
            xa[mt][0], xa[mt][1], xa[mt][2], xa[mt][3]);
    const uint4* w1f = (const uint4*)((const char*)g_w1 + (size_t)(m * 8 + wid) * 2048) + lane;
#pragma unroll
    for (int pq = 0; pq < 4; ++pq) {
      uint4 bf = w1f[pq * 32];
      float pa[4][2][4];
#pragma unroll
      for (int mt = 0; mt < 4; ++mt) {
#pragma unroll
        for (int tn = 0; tn < 2; ++tn)
#pragma unroll
          for (int i = 0; i < 4; ++i) pa[mt][tn][i] = 0.f;
        mma16816(pa[mt][0], xa[mt][0], xa[mt][1], xa[mt][2], xa[mt][3], bf.x, bf.y);
        mma16816(pa[mt][1], xa[mt][0], xa[mt][1], xa[mt][2], xa[mt][3], bf.z, bf.w);
      }
#pragma unroll
      for (int mt = 0; mt < 4; ++mt)
#pragma unroll
        for (int tn = 0; tn < 2; ++tn) {
          int col = wid * 64 + pq * 16 + tn * 8 + lc2;
          int row0 = mt * 16 + lr;
          *(__half2*)(sm + OF_A + swA(row0, col * 2)) =
              __floats2half2_rn(fmaxf(pa[mt][tn][0], 0.f), fmaxf(pa[mt][tn][1], 0.f));
          *(__half2*)(sm + OF_A + swA(row0 + 8, col * 2)) =
              __floats2half2_rn(fmaxf(pa[mt][tn][2], 0.f), fmaxf(pa[mt][tn][3], 0.f));
        }
    }
  }
  __syncthreads();   // h1 complete; A-tile read-only for the REST of the kernel

  const float* b2 = (g < 3) ? (p.ent_b2 + m * 512) : p.pad_b2;

  // ---- all four nq quarters in one CTA, barrier-free ----
  for (int nq = 0; nq < 4; ++nq) {
    float acc[2][4][4];
#pragma unroll
    for (int mt = 0; mt < 2; ++mt)
#pragma unroll
      for (int nt = 0; nt < 4; ++nt)
#pragma unroll
        for (int i = 0; i < 4; ++i) acc[mt][nt][i] = 0.f;

    const char* wbase = (const char*)g_w2 +
        (size_t)(m * 4 + nq) * 131072 + nw * 1024 + lane * 16;
    // 3-stage register ring: lookahead = 2 k16 iterations (~128 cyc of mma cover)
    uint4 b0a = *(const uint4*)(wbase);
    uint4 b0b = *(const uint4*)(wbase + 512);
    uint4 b1a = *(const uint4*)(wbase + 4096);
    uint4 b1b = *(const uint4*)(wbase + 4096 + 512);
#pragma unroll 8
    for (int kt = 0; kt < 32; ++kt) {
      uint4 b2a, b2b;
      if (kt < 30) {
        b2a = *(const uint4*)(wbase + (kt + 2) * 4096);
        b2b = *(const uint4*)(wbase + (kt + 2) * 4096 + 512);
      }
      uint32_t A0[4], A1[4];
      ldsm4(smb + OF_A + swA(mw * 32 + ag_r, (kt * 16 + ag_k) * 2), A0[0], A0[1], A0[2], A0[3]);
      ldsm4(smb + OF_A + swA(mw * 32 + 16 + ag_r, (kt * 16 + ag_k) * 2), A1[0], A1[1], A1[2], A1[3]);
      mma16816(acc[0][0], A0[0], A0[1], A0[2], A0[3], b0a.x, b0a.y);
      mma16816(acc[1][0], A1[0], A1[1], A1[2], A1[3], b0a.x, b0a.y);
      mma16816(acc[0][1], A0[0], A0[1], A0[2], A0[3], b0a.z, b0a.w);
      mma16816(acc[1][1], A1[0], A1[1], A1[2], A1[3], b0a.z, b0a.w);
      mma16816(acc[0][2], A0[0], A0[1], A0[2], A0[3], b0b.x, b0b.y);
      mma16816(acc[1][2], A1[0], A1[1], A1[2], A1[3], b0b.x, b0b.y);
      mma16816(acc[0][3], A0[0], A0[1], A0[2], A0[3], b0b.z, b0b.w);
      mma16816(acc[1][3], A1[0], A1[1], A1[2], A1[3], b0b.z, b0b.w);
      b0a = b1a; b0b = b1b; b1a = b2a; b1b = b2b;
    }

    // ---- heads B frags: issue LDGs early to overlap with bias/pack ----
    const uint4* hf = (const uint4*)((const char*)g_hd +
        (size_t)((m * 4 + nq) * 4 + nw) * 2048) + lane;
    uint4 h00 = hf[0], h01 = hf[32];
    uint4 h10 = hf[64], h11 = hf[96];

    // ---- h2 (bias+relu) -> A-frags IN REGISTERS (C-frag == A-frag identity) ----
    uint32_t afh[2][2][4];
#pragma unroll
    for (int q = 0; q < 2; ++q) {
      int ce = nq * 128 + nw * 32 + q * 16 + lc2;   // even tile cols; odd tile +8
      float be0 = __ldg(b2 + ce),     be1 = __ldg(b2 + ce + 1);
      float bo0 = __ldg(b2 + ce + 8), bo1 = __ldg(b2 + ce + 9);
#pragma unroll
      for (int mt = 0; mt < 2; ++mt) {
        afh[mt][q][0] = packrelu(acc[mt][2 * q][0] + be0, acc[mt][2 * q][1] + be1);
        afh[mt][q][1] = packrelu(acc[mt][2 * q][2] + be0, acc[mt][2 * q][3] + be1);
        afh[mt][q][2] = packrelu(acc[mt][2 * q + 1][0] + bo0, acc[mt][2 * q + 1][1] + bo1);
        afh[mt][q][3] = packrelu(acc[mt][2 * q + 1][2] + bo0, acc[mt][2 * q + 1][3] + bo1);
      }
    }

    // ---- heads GEMM from registers: k-slice nq*128 + nw*32 (+q*16) ----
    float hacc[2][3][4];
#pragma unroll
    for (int mt = 0; mt < 2; ++mt)
#pragma unroll
      for (int nt = 0; nt < 3; ++nt)
#pragma unroll
        for (int i = 0; i < 4; ++i) hacc[mt][nt][i] = 0.f;
#pragma unroll
    for (int mt = 0; mt < 2; ++mt) {
      mma16816(hacc[mt][0], afh[mt][0][0], afh[mt][0][1], afh[mt][0][2], afh[mt][0][3], h00.x, h00.y);
      mma16816(hacc[mt][1], afh[mt][0][0], afh[mt][0][1], afh[mt][0][2], afh[mt][0][3], h00.z, h00.w);
      mma16816(hacc[mt][2], afh[mt][0][0], afh[mt][0][1], afh[mt][0][2], afh[mt][0][3], h01.x, h01.y);
      mma16816(hacc[mt][0], afh[mt][1][0], afh[mt][1][1], afh[mt][1][2], afh[mt][1][3], h10.x, h10.y);
      mma16816(hacc[mt][1], afh[mt][1][0], afh[mt][1][1], afh[mt][1][2], afh[mt][1][3], h10.z, h10.w);
      mma16816(hacc[mt][2], afh[mt][1][0], afh[mt][1][1], afh[mt][1][2], afh[mt][1][3], h11.x, h11.y);
    }

    // ---- accumulate into g_part via global atomics (no SMEM, no syncs) ----
#pragma unroll
    for (int mt = 0; mt < 2; ++mt)
#pragma unroll
      for (int nt = 0; nt < 3; ++nt) {
        int col = nt * 8 + lc2;
        if (col < 22) {
          int row0 = mw * 32 + mt * 16 + lr;
          size_t b = ((size_t)g * 32768 + s0 + row0) * 22 + col;
          atomicAdd(&g_part[b],              hacc[mt][nt][0]);
          atomicAdd(&g_part[b + 1],          hacc[mt][nt][1]);
          atomicAdd(&g_part[b + 8 * 22],     hacc[mt][nt][2]);
          atomicAdd(&g_part[b + 8 * 22 + 1], hacc[mt][nt][3]);
        }
      }
  }
}

__global__ void epilogue_kernel(PE p, int B) {
  int s = blockIdx.x * blockDim.x + threadIdx.x;
  if (s >= B) return;
  float hd[9][22];
#pragma unroll
  for (int q = 0; q < 9; ++q) {
    const float* pp = g_part + ((size_t)q * 32768 + s) * 22;
#pragma unroll
    for (int c = 0; c < 22; ++c) hd[q][c] = pp[c];
  }
  float mx = -1e30f;
#pragma unroll
  for (int q = 3; q < 9; ++q) mx = fmaxf(mx, hd[q][21]);
  float den = 0.f, agg[21];
#pragma unroll
  for (int c = 0; c < 21; ++c) agg[c] = 0.f;
#pragma unroll
  for (int q = 3; q < 9; ++q) {
    float w = expf(hd[q][21] - mx);
    den += w;
#pragma unroll
    for (int c = 0; c < 21; ++c) agg[c] = fmaf(w, hd[q][c], agg[c]);
  }
  float inv = 1.f / den;

  float* o = p.out + (size_t)s * 105;
  float pos[4][3], coef[4][9], cov[4][9];
  for (int e = 0; e < 3; ++e) {
    for (int d = 0; d < 3; ++d) pos[e][d]  = hd[e][d] + p.ent_bpos[e * 3 + d];
    for (int c = 0; c < 9; ++c) coef[e][c] = hd[e][3 + c] + p.ent_bc[e * 9 + c];
    for (int c = 0; c < 9; ++c) cov[e][c]  = softplusf(hd[e][12 + c] + p.ent_bv[e * 9 + c]);
  }
  for (int d = 0; d < 3; ++d) pos[3][d]  = agg[d] * inv + p.b_bpos[d];
  for (int c = 0; c < 9; ++c) coef[3][c] = agg[3 + c] * inv + p.b_bc[c];
  for (int c = 0; c < 9; ++c) cov[3][c]  = softplusf(agg[12 + c] * inv + p.b_bv[c]);
  for (int i = 0; i < 4; ++i) {
    float x = pos[i][0], y = pos[i][1], z = pos[i][2];
    for (int c = 0; c < 9; ++c) o[i * 24 + c]     = coef[i][c];
    for (int c = 0; c < 9; ++c) o[i * 24 + 9 + c] = cov[i][c];
    o[i * 24 + 18] = (4096.f - x) * 1e-3f;
    o[i * 24 + 19] = (4096.f + x) * 1e-3f;
    o[i * 24 + 20] = (5120.f - y) * 1e-3f;
    o[i * 24 + 21] = (5120.f + y) * 1e-3f;
    o[i * 24 + 22] = z * 1e-3f;
    o[i * 24 + 23] = (2044.f - z) * 1e-3f;
  }
  const int iu[6] = {0, 0, 0, 1, 1, 2}, ju[6] = {1, 2, 3, 2, 3, 3};
  for (int q = 0; q < 6; ++q) {
    int i = iu[q], j = ju[q];
    float d2 = 0.f, cd = 0.f;
    for (int d = 0; d < 3; ++d) { float df = pos[i][d] - pos[j][d]; d2 = fmaf(df, df, d2); }
    for (int c = 0; c < 9; ++c) cd = fmaf(coef[i][c], coef[j][c], cd);
    o[96 + q] = expf(-2.f * d2) * cd;
  }
  for (int d = 0; d < 3; ++d) {
    float ga = p.gs_b[d];
    for (int k = 0; k < 10; ++k)
      ga = fmaf(p.tokens[(size_t)s * 100 + 90 + k], p.gs_W[k * 3 + d], ga);
    o[102 + d] = ga;
  }
}

extern "C" void kernel_launch(void* const* d_in, const int* in_sizes, int n_in,
                              void* d_out, int out_size) {
  pack_kernel<<<512, 256>>>(
      (const float*)d_in[3],  (const float*)d_in[13],
      (const float*)d_in[1],  (const float*)d_in[2],
      (const float*)d_in[11], (const float*)d_in[12],
      (const float*)d_in[5],  (const float*)d_in[7],  (const float*)d_in[9],
      (const float*)d_in[17], (const float*)d_in[19], (const float*)d_in[21],
      (const float*)d_in[15]);

  int B = in_sizes[0] / 100;

  PM pm;
  pm.tokens = (const float*)d_in[0];
  pm.ent_b2 = (const float*)d_in[4];
  pm.pad_b2 = (const float*)d_in[14];
  cudaFuncSetAttribute(spectral_mma_kernel, cudaFuncAttributeMaxDynamicSharedMemorySize, SMEM_SZ);
  dim3 grid(B / 64, 9, 1);
  spectral_mma_kernel<<<grid, NTH, SMEM_SZ>>>(pm);

  PE pe;
  pe.tokens = (const float*)d_in[0];
  pe.ent_bpos = (const float*)d_in[6];
  pe.ent_bc = (const float*)d_in[8];
  pe.ent_bv = (const float*)d_in[10];
  pe.b_bpos = (const float*)d_in[18];
  pe.b_bc = (const float*)d_in[20];
  pe.b_bv = (const float*)d_in[22];
  pe.gs_W = (const float*)d_in[23];
  pe.gs_b = (const float*)d_in[24];
  pe.out = (float*)d_out;
  epilogue_kernel<<<(B + 127) / 128, 128>>>(pe, B);
}

// round 16
// speedup vs baseline: 1.5777x; 1.1059x over previous
#include <cuda_runtime.h>
#include <cuda_fp16.h>
#include <math.h>
#include <stdint.h>

// ---------------- packed fp16 weights (all fragment-ordered for direct LDG) ----
// g_w2: [m4][nq4][kt32][nw4][grp2][lane32][4 halves]
// g_w1: [m4][w8][pq4][lane32][8 halves]   (k10 = b1 folded)
// g_hd: [m4][nq4][nw4][q2][tp2][lane32][4 halves]
__device__ __align__(16) __half g_w2[1048576];
__device__ __align__(16) __half g_w1[32768];
__device__ __align__(16) __half g_hd[65536];
// head sums: [g (9)][sample (32768)][22] f32 — written once per (g, block) CTA, no atomics
__device__ float g_part[9 * 32768 * 22];

struct PM {
  const float *tokens;
  const float *ent_b2, *pad_b2;
};
struct PE {
  const float *tokens;
  const float *ent_bpos, *ent_bc, *ent_bv;
  const float *b_bpos, *b_bc, *b_bv;
  const float *gs_W, *gs_b;
  float *out;
};

__global__ void pack_kernel(const float* eW2, const float* pW2,
                            const float* eW1, const float* eb1,
                            const float* pW1, const float* pb1,
                            const float* eWpos, const float* eWc, const float* eWv,
                            const float* bWpos, const float* bWc, const float* bWv,
                            const float* attnW) {
  int tid = blockIdx.x * blockDim.x + threadIdx.x;
  int NT = gridDim.x * blockDim.x;
  for (int idx = tid; idx < 4 * 512 * 512; idx += NT) {
    int m = idx >> 18, r = idx & 262143, k = r >> 9, n = r & 511;
    float v = (m < 3) ? eW2[m * 262144 + k * 512 + n] : pW2[k * 512 + n];
    int nq = n >> 7, nl = n & 127;
    int nw = nl >> 5, nt = (nl >> 3) & 3;
    int grp = nt >> 1, odd = nt & 1;
    int kt = k >> 4, kk = k & 15;
    int lane = (nl & 7) * 4 + ((kk & 7) >> 1);
    int dst = ((((m * 4 + nq) * 32 + kt) * 4 + nw) * 2 + grp) * 256 +
              lane * 8 + odd * 4 + ((kk >> 3) & 1) * 2 + (kk & 1);
    g_w2[dst] = __float2half(v);
  }
  for (int idx = tid; idx < 4 * 512 * 16; idx += NT) {
    int m = idx >> 13, r = idx & 8191, n = r >> 4, k = r & 15;
    float v = 0.f;
    if (k < 10)       v = (m < 3) ? eW1[m * 5120 + k * 512 + n] : pW1[k * 512 + n];
    else if (k == 10) v = (m < 3) ? eb1[m * 512 + n] : pb1[n];
    int w = n >> 6, pq = (n >> 4) & 3, odd = (n >> 3) & 1;
    int lane = (n & 7) * 4 + ((k & 7) >> 1);
    int dst = ((m * 8 + w) * 4 + pq) * 256 + lane * 8 + odd * 4 + ((k >> 3) & 1) * 2 + (k & 1);
    g_w1[dst] = __float2half(v);
  }
  for (int idx = tid; idx < 4 * 32 * 512; idx += NT) {
    int m = idx >> 14, r = idx & 16383, n = r >> 9, k = r & 511;
    float v = 0.f;
    if (m < 3) {
      if (n < 3)       v = eWpos[m * 1536 + k * 3 + n];
      else if (n < 12) v = eWc[m * 4608 + k * 9 + (n - 3)];
      else if (n < 21) v = eWv[m * 4608 + k * 9 + (n - 12)];
    } else {
      if (n < 3)       v = bWpos[k * 3 + n];
      else if (n < 12) v = bWc[k * 9 + (n - 3)];
      else if (n < 21) v = bWv[k * 9 + (n - 12)];
      else if (n == 21) v = attnW[k];
    }
    int nq = k >> 7, kl = k & 127;
    int nw = kl >> 5, q = (kl >> 4) & 1, kk = kl & 15;
    int tp = n >> 4, odd = (n >> 3) & 1;
    int lane = (n & 7) * 4 + ((kk & 7) >> 1);
    int dst = ((((m * 4 + nq) * 4 + nw) * 2 + q) * 2 + tp) * 256 +
              lane * 8 + odd * 4 + ((kk >> 3) & 1) * 2 + (kk & 1);
    g_hd[dst] = __float2half(v);
  }
}

// ---------------- mma helpers ----------------
__device__ __forceinline__ void ldsm4(uint32_t a, uint32_t& r0, uint32_t& r1,
                                      uint32_t& r2, uint32_t& r3) {
  asm volatile("ldmatrix.sync.aligned.m8n8.x4.shared.b16 {%0,%1,%2,%3}, [%4];"
               : "=r"(r0), "=r"(r1), "=r"(r2), "=r"(r3) : "r"(a));
}
__device__ __forceinline__ void mma16816(float* c, uint32_t a0, uint32_t a1,
                                         uint32_t a2, uint32_t a3,
                                         uint32_t b0, uint32_t b1) {
  asm volatile(
      "mma.sync.aligned.m16n8k16.row.col.f32.f16.f16.f32 "
      "{%0,%1,%2,%3},{%4,%5,%6,%7},{%8,%9},{%0,%1,%2,%3};"
      : "+f"(c[0]), "+f"(c[1]), "+f"(c[2]), "+f"(c[3])
      : "r"(a0), "r"(a1), "r"(a2), "r"(a3), "r"(b0), "r"(b1));
}
__device__ __forceinline__ uint32_t packrelu(float a, float b) {
  __half2 h = __floats2half2_rn(fmaxf(a, 0.f), fmaxf(b, 0.f));
  return *(uint32_t*)&h;
}
__device__ __forceinline__ int swA(int row, int kbyte) {
  return (row * 1024 + kbyte) ^ ((row & 7) << 4);
}

// ---------------- smem layout ----------------
#define NTH 256
static constexpr int OF_A  = 0;        // h1 tile: 64 rows x 1024B swizzled = 65,536 (never overwritten)
static constexpr int OF_SC = 65536;    // x-tile 2,048 (phase A only)
static constexpr int OF_P  = 67584;    // s_part 64 x 24 f32 = 6,144
static constexpr int SMEM_SZ = 73728;  // 72 KB -> 3 CTAs/SM

__device__ __forceinline__ float softplusf(float x) { return (x > 20.f) ? x : log1pf(expf(x)); }

__global__ void __launch_bounds__(NTH, 3) spectral_mma_kernel(PM p) {
  extern __shared__ __align__(128) unsigned char sm[];
  const uint32_t smb = (uint32_t)__cvta_generic_to_shared(sm);
  const int t = threadIdx.x, wid = t >> 5, lane = t & 31;
  const int g = blockIdx.y;
  const int m = (g < 3) ? g : 3;
  const int s0 = blockIdx.x * 64;
  const int mw = wid & 1, nw = wid >> 1;                // 2 M-warps x 4 N-warps (64x128)
  const int ag_r = ((lane >> 3) & 1) * 8 + (lane & 7);
  const int ag_k = ((lane >> 4) & 1) * 8;
  const int lr = lane >> 2, lc2 = (lane & 3) * 2;

  // ---- prologue: x-tile (64x16, ones at k=10) + zero s_part ----
  for (int i = t; i < 64 * 16; i += NTH) {
    int s = i >> 4, k = i & 15;
    float v = (k < 10) ? p.tokens[(size_t)(s0 + s) * 100 + g * 10 + k] : (k == 10 ? 1.f : 0.f);
    *(__half*)(sm + OF_SC + s * 32 + k * 2) = __float2half(v);
  }
  for (int i = t; i < 64 * 24; i += NTH) ((float*)(sm + OF_P))[i] = 0.f;
  __syncthreads();

  // ---- phase A: h1 = relu(x @ W1T) -> swizzled A-tile; warp wid covers cols wid*64 ----
  {
    uint32_t xa[4][4];
#pragma unroll
    for (int mt = 0; mt < 4; ++mt)
      ldsm4(smb + OF_SC + (mt * 16 + ag_r) * 32 + ag_k * 2,
            xa[mt][0], xa[mt][1], xa[mt][2], xa[mt][3]);
    const uint4* w1f = (const uint4*)((const char*)g_w1 + (size_t)(m * 8 + wid) * 2048) + lane;
#pragma unroll
    for (int pq = 0; pq < 4; ++pq) {
      uint4 bf = w1f[pq * 32];
      float pa[4][2][4];
#pragma unroll
      for (int mt = 0; mt < 4; ++mt) {
#pragma unroll
        for (int tn = 0; tn < 2; ++tn)
#pragma unroll
          for (int i = 0; i < 4; ++i) pa[mt][tn][i] = 0.f;
        mma16816(pa[mt][0], xa[mt][0], xa[mt][1], xa[mt][2], xa[mt][3], bf.x, bf.y);
        mma16816(pa[mt][1], xa[mt][0], xa[mt][1], xa[mt][2], xa[mt][3], bf.z, bf.w);
      }
#pragma unroll
      for (int mt = 0; mt < 4; ++mt)
#pragma unroll
        for (int tn = 0; tn < 2; ++tn) {
          int col = wid * 64 + pq * 16 + tn * 8 + lc2;
          int row0 = mt * 16 + lr;
          *(__half2*)(sm + OF_A + swA(row0, col * 2)) =
              __floats2half2_rn(fmaxf(pa[mt][tn][0], 0.f), fmaxf(pa[mt][tn][1], 0.f));
          *(__half2*)(sm + OF_A + swA(row0 + 8, col * 2)) =
              __floats2half2_rn(fmaxf(pa[mt][tn][2], 0.f), fmaxf(pa[mt][tn][3], 0.f));
        }
    }
  }
  __syncthreads();   // h1 complete; A-tile read-only for the REST of the kernel

  const float* b2 = (g < 3) ? (p.ent_b2 + m * 512) : p.pad_b2;
  float* sp = (float*)(sm + OF_P);

  // ---- all four nq quarters in one CTA, barrier-free ----
  for (int nq = 0; nq < 4; ++nq) {
    float acc[2][4][4];
#pragma unroll
    for (int mt = 0; mt < 2; ++mt)
#pragma unroll
      for (int nt = 0; nt < 4; ++nt)
#pragma unroll
        for (int i = 0; i < 4; ++i) acc[mt][nt][i] = 0.f;

    const char* wbase = (const char*)g_w2 +
        (size_t)(m * 4 + nq) * 131072 + nw * 1024 + lane * 16;
    // B: depth-1 prefetch; A: double-buffered ldsm frags
    uint4 bc0 = *(const uint4*)(wbase);
    uint4 bc1 = *(const uint4*)(wbase + 512);
    uint32_t Ac0[4], Ac1[4], An0[4], An1[4];
    ldsm4(smb + OF_A + swA(mw * 32 + ag_r, ag_k * 2), Ac0[0], Ac0[1], Ac0[2], Ac0[3]);
    ldsm4(smb + OF_A + swA(mw * 32 + 16 + ag_r, ag_k * 2), Ac1[0], Ac1[1], Ac1[2], Ac1[3]);
#pragma unroll 8
    for (int kt = 0; kt < 32; ++kt) {
      uint4 bn0, bn1;
      if (kt < 31) {
        bn0 = *(const uint4*)(wbase + (kt + 1) * 4096);
        bn1 = *(const uint4*)(wbase + (kt + 1) * 4096 + 512);
        ldsm4(smb + OF_A + swA(mw * 32 + ag_r, ((kt + 1) * 16 + ag_k) * 2),
              An0[0], An0[1], An0[2], An0[3]);
        ldsm4(smb + OF_A + swA(mw * 32 + 16 + ag_r, ((kt + 1) * 16 + ag_k) * 2),
              An1[0], An1[1], An1[2], An1[3]);
      }
      mma16816(acc[0][0], Ac0[0], Ac0[1], Ac0[2], Ac0[3], bc0.x, bc0.y);
      mma16816(acc[1][0], Ac1[0], Ac1[1], Ac1[2], Ac1[3], bc0.x, bc0.y);
      mma16816(acc[0][1], Ac0[0], Ac0[1], Ac0[2], Ac0[3], bc0.z, bc0.w);
      mma16816(acc[1][1], Ac1[0], Ac1[1], Ac1[2], Ac1[3], bc0.z, bc0.w);
      mma16816(acc[0][2], Ac0[0], Ac0[1], Ac0[2], Ac0[3], bc1.x, bc1.y);
      mma16816(acc[1][2], Ac1[0], Ac1[1], Ac1[2], Ac1[3], bc1.x, bc1.y);
      mma16816(acc[0][3], Ac0[0], Ac0[1], Ac0[2], Ac0[3], bc1.z, bc1.w);
      mma16816(acc[1][3], Ac1[0], Ac1[1], Ac1[2], Ac1[3], bc1.z, bc1.w);
      bc0 = bn0; bc1 = bn1;
#pragma unroll
      for (int i = 0; i < 4; ++i) { Ac0[i] = An0[i]; Ac1[i] = An1[i]; }
    }

    // ---- heads B frags: issue LDGs early ----
    const uint4* hf = (const uint4*)((const char*)g_hd +
        (size_t)((m * 4 + nq) * 4 + nw) * 2048) + lane;
    uint4 h00 = hf[0], h01 = hf[32];
    uint4 h10 = hf[64], h11 = hf[96];

    // ---- h2 (bias+relu) -> A-frags IN REGISTERS ----
    uint32_t afh[2][2][4];
#pragma unroll
    for (int q = 0; q < 2; ++q) {
      int ce = nq * 128 + nw * 32 + q * 16 + lc2;
      float be0 = __ldg(b2 + ce),     be1 = __ldg(b2 + ce + 1);
      float bo0 = __ldg(b2 + ce + 8), bo1 = __ldg(b2 + ce + 9);
#pragma unroll
      for (int mt = 0; mt < 2; ++mt) {
        afh[mt][q][0] = packrelu(acc[mt][2 * q][0] + be0, acc[mt][2 * q][1] + be1);
        afh[mt][q][1] = packrelu(acc[mt][2 * q][2] + be0, acc[mt][2 * q][3] + be1);
        afh[mt][q][2] = packrelu(acc[mt][2 * q + 1][0] + bo0, acc[mt][2 * q + 1][1] + bo1);
        afh[mt][q][3] = packrelu(acc[mt][2 * q + 1][2] + bo0, acc[mt][2 * q + 1][3] + bo1);
      }
    }

    // ---- heads GEMM from registers ----
    float hacc[2][3][4];
#pragma unroll
    for (int mt = 0; mt < 2; ++mt)
#pragma unroll
      for (int nt = 0; nt < 3; ++nt)
#pragma unroll
        for (int i = 0; i < 4; ++i) hacc[mt][nt][i] = 0.f;
#pragma unroll
    for (int mt = 0; mt < 2; ++mt) {
      mma16816(hacc[mt][0], afh[mt][0][0], afh[mt][0][1], afh[mt][0][2], afh[mt][0][3], h00.x, h00.y);
      mma16816(hacc[mt][1], afh[mt][0][0], afh[mt][0][1], afh[mt][0][2], afh[mt][0][3], h00.z, h00.w);
      mma16816(hacc[mt][2], afh[mt][0][0], afh[mt][0][1], afh[mt][0][2], afh[mt][0][3], h01.x, h01.y);
      mma16816(hacc[mt][0], afh[mt][1][0], afh[mt][1][1], afh[mt][1][2], afh[mt][1][3], h10.x, h10.y);
      mma16816(hacc[mt][1], afh[mt][1][0], afh[mt][1][1], afh[mt][1][2], afh[mt][1][3], h10.z, h10.w);
      mma16816(hacc[mt][2], afh[mt][1][0], afh[mt][1][1], afh[mt][1][2], afh[mt][1][3], h11.x, h11.y);
    }

    // ---- reduce into SMEM s_part (cheap ATOMS; all contributions intra-CTA) ----
#pragma unroll
    for (int mt = 0; mt < 2; ++mt)
#pragma unroll
      for (int nt = 0; nt < 3; ++nt) {
        int col = nt * 8 + lc2;
        if (col < 22) {
          int row0 = mw * 32 + mt * 16 + lr;
          atomicAdd(sp + row0 * 24 + col,           hacc[mt][nt][0]);
          atomicAdd(sp + row0 * 24 + col + 1,       hacc[mt][nt][1]);
          atomicAdd(sp + (row0 + 8) * 24 + col,     hacc[mt][nt][2]);
          atomicAdd(sp + (row0 + 8) * 24 + col + 1, hacc[mt][nt][3]);
        }
      }
  }
  __syncthreads();

  // ---- single non-atomic store of head sums ----
  for (int i = t; i < 64 * 22; i += NTH) {
    int s = i / 22, c = i - s * 22;
    g_part[((size_t)g * 32768 + s0 + s) * 22 + c] = sp[s * 24 + c];
  }
}

__global__ void epilogue_kernel(PE p, int B) {
  int s = blockIdx.x * blockDim.x + threadIdx.x;
  if (s >= B) return;
  float hd[9][22];
#pragma unroll
  for (int q = 0; q < 9; ++q) {
    const float* pp = g_part + ((size_t)q * 32768 + s) * 22;
#pragma unroll
    for (int c = 0; c < 22; ++c) hd[q][c] = pp[c];
  }
  float mx = -1e30f;
#pragma unroll
  for (int q = 3; q < 9; ++q) mx = fmaxf(mx, hd[q][21]);
  float den = 0.f, agg[21];
#pragma unroll
  for (int c = 0; c < 21; ++c) agg[c] = 0.f;
#pragma unroll
  for (int q = 3; q < 9; ++q) {
    float w = expf(hd[q][21] - mx);
    den += w;
#pragma unroll
    for (int c = 0; c < 21; ++c) agg[c] = fmaf(w, hd[q][c], agg[c]);
  }
  float inv = 1.f / den;

  float* o = p.out + (size_t)s * 105;
  float pos[4][3], coef[4][9], cov[4][9];
  for (int e = 0; e < 3; ++e) {
    for (int d = 0; d < 3; ++d) pos[e][d]  = hd[e][d] + p.ent_bpos[e * 3 + d];
    for (int c = 0; c < 9; ++c) coef[e][c] = hd[e][3 + c] + p.ent_bc[e * 9 + c];
    for (int c = 0; c < 9; ++c) cov[e][c]  = softplusf(hd[e][12 + c] + p.ent_bv[e * 9 + c]);
  }
  for (int d = 0; d < 3; ++d) pos[3][d]  = agg[d] * inv + p.b_bpos[d];
  for (int c = 0; c < 9; ++c) coef[3][c] = agg[3 + c] * inv + p.b_bc[c];
  for (int c = 0; c < 9; ++c) cov[3][c]  = softplusf(agg[12 + c] * inv + p.b_bv[c]);
  for (int i = 0; i < 4; ++i) {
    float x = pos[i][0], y = pos[i][1], z = pos[i][2];
    for (int c = 0; c < 9; ++c) o[i * 24 + c]     = coef[i][c];
    for (int c = 0; c < 9; ++c) o[i * 24 + 9 + c] = cov[i][c];
    o[i * 24 + 18] = (4096.f - x) * 1e-3f;
    o[i * 24 + 19] = (4096.f + x) * 1e-3f;
    o[i * 24 + 20] = (5120.f - y) * 1e-3f;
    o[i * 24 + 21] = (5120.f + y) * 1e-3f;
    o[i * 24 + 22] = z * 1e-3f;
    o[i * 24 + 23] = (2044.f - z) * 1e-3f;
  }
  const int iu[6] = {0, 0, 0, 1, 1, 2}, ju[6] = {1, 2, 3, 2, 3, 3};
  for (int q = 0; q < 6; ++q) {
    int i = iu[q], j = ju[q];
    float d2 = 0.f, cd = 0.f;
    for (int d = 0; d < 3; ++d) { float df = pos[i][d] - pos[j][d]; d2 = fmaf(df, df, d2); }
    for (int c = 0; c < 9; ++c) cd = fmaf(coef[i][c], coef[j][c], cd);
    o[96 + q] = expf(-2.f * d2) * cd;
  }
  for (int d = 0; d < 3; ++d) {
    float ga = p.gs_b[d];
    for (int k = 0; k < 10; ++k)
      ga = fmaf(p.tokens[(size_t)s * 100 + 90 + k], p.gs_W[k * 3 + d], ga);
    o[102 + d] = ga;
  }
}

extern "C" void kernel_launch(void* const* d_in, const int* in_sizes, int n_in,
                              void* d_out, int out_size) {
  pack_kernel<<<512, 256>>>(
      (const float*)d_in[3],  (const float*)d_in[13],
      (const float*)d_in[1],  (const float*)d_in[2],
      (const float*)d_in[11], (const float*)d_in[12],
      (const float*)d_in[5],  (const float*)d_in[7],  (const float*)d_in[9],
      (const float*)d_in[17], (const float*)d_in[19], (const float*)d_in[21],
      (const float*)d_in[15]);

  int B = in_sizes[0] / 100;

  PM pm;
  pm.tokens = (const float*)d_in[0];
  pm.ent_b2 = (const float*)d_in[4];
  pm.pad_b2 = (const float*)d_in[14];
  cudaFuncSetAttribute(spectral_mma_kernel, cudaFuncAttributeMaxDynamicSharedMemorySize, SMEM_SZ);
  dim3 grid(B / 64, 9, 1);
  spectral_mma_kernel<<<grid, NTH, SMEM_SZ>>>(pm);

  PE pe;
  pe.tokens = (const float*)d_in[0];
  pe.ent_bpos = (const float*)d_in[6];
  pe.ent_bc = (const float*)d_in[8];
  pe.ent_bv = (const float*)d_in[10];
  pe.b_bpos = (const float*)d_in[18];
  pe.b_bc = (const float*)d_in[20];
  pe.b_bv = (const float*)d_in[22];
  pe.gs_W = (const float*)d_in[23];
  pe.gs_b = (const float*)d_in[24];
  pe.out = (float*)d_out;
  epilogue_kernel<<<(B + 127) / 128, 128>>>(pe, B);
}